// round 7
// baseline (speedup 1.0000x reference)
#include <cuda_runtime.h>
#include <cuda_bf16.h>
#include <cstdint>

// ---------------- problem constants ----------------
#define T_SEQ 512
#define BB    16
#define HH    1024
#define EE    512
#define VV    32000
#define G4H   4096
#define M_ROWS (BB * T_SEQ)                     // 8192
#define LOGN  ((size_t)M_ROWS * (size_t)VV)     // 262,144,000

// ---------------- device scratch (static globals: allowed) ----------------
__device__ float g_xg[(size_t)T_SEQ * BB * G4H];      // 134 MB, reused per layer
__device__ float g_out0[(size_t)M_ROWS * HH];         // layer-0 h sequence
__device__ float g_out1[(size_t)M_ROWS * HH];         // layer-1 h sequence
__device__ float g_hbuf[2 * HH * BB];                 // double buffer, [j][b] layout
__device__ int   g_flags[128];                        // per-CTA step flags
__device__ __nv_bfloat16 g_A2[(size_t)M_ROWS * 3072]; // 50 MB  activations (hi|hi|lo)
__device__ __nv_bfloat16 g_B2[(size_t)VV * 3072];     // 197 MB Wfc (hi|lo|hi)
__device__ __nv_bfloat16 g_W2[(size_t)G4H * 3072];    // 25 MB  Wih (hi|lo|hi)

// ---------------- f32x2 packed-FMA helpers ----------------
typedef unsigned long long u64;
__device__ __forceinline__ u64 pack2(float v) {
    u64 r; asm("mov.b64 %0, {%1, %1};" : "=l"(r) : "f"(v)); return r;
}
__device__ __forceinline__ void ffma2(u64& c, u64 a, u64 b) {
    asm("fma.rn.f32x2 %0, %1, %2, %0;" : "+l"(c) : "l"(a), "l"(b));
}
__device__ __forceinline__ float2 unpack2(u64 v) {
    float lo, hi; asm("mov.b64 {%0, %1}, %2;" : "=f"(lo), "=f"(hi) : "l"(v));
    float2 f; f.x = lo; f.y = hi; return f;
}

// ---------------- flag load/store: acquire/release, gpu scope ----------------
__device__ __forceinline__ int ld_acq(const int* p) {
    int v;
    asm volatile("ld.global.acquire.gpu.s32 %0, [%1];" : "=r"(v) : "l"(p) : "memory");
    return v;
}
__device__ __forceinline__ void st_rel(int* p, int v) {
    asm volatile("st.global.release.gpu.s32 [%0], %1;" :: "l"(p), "r"(v) : "memory");
}

// ---------------- base-ISA async-copy / ldmatrix / mma helpers ----------------
__device__ __forceinline__ uint32_t smem_u32(const void* p) {
    uint32_t a;
    asm("{ .reg .u64 t; cvta.to.shared.u64 t, %1; cvt.u32.u64 %0, t; }" : "=r"(a) : "l"(p));
    return a;
}
__device__ __forceinline__ void cpa16(uint32_t dst, const void* src) {
    asm volatile("cp.async.cg.shared.global [%0], [%1], 16;" :: "r"(dst), "l"(src));
}
__device__ __forceinline__ void cpa_commit() { asm volatile("cp.async.commit_group;" ::: "memory"); }
template<int N> __device__ __forceinline__ void cpa_wait() {
    asm volatile("cp.async.wait_group %0;" :: "n"(N) : "memory");
}
__device__ __forceinline__ void ldsm4(uint32_t& r0, uint32_t& r1, uint32_t& r2, uint32_t& r3,
                                      uint32_t a) {
    asm volatile("ldmatrix.sync.aligned.m8n8.x4.shared.b16 {%0,%1,%2,%3}, [%4];"
                 : "=r"(r0), "=r"(r1), "=r"(r2), "=r"(r3) : "r"(a));
}
__device__ __forceinline__ void mma_bf16(float* c, const uint32_t* a, const uint32_t* b) {
    asm volatile(
        "mma.sync.aligned.m16n8k16.row.col.f32.bf16.bf16.f32 "
        "{%0,%1,%2,%3}, {%4,%5,%6,%7}, {%8,%9}, {%0,%1,%2,%3};"
        : "+f"(c[0]), "+f"(c[1]), "+f"(c[2]), "+f"(c[3])
        : "r"(a[0]), "r"(a[1]), "r"(a[2]), "r"(a[3]), "r"(b[0]), "r"(b[1]));
}

// ---------------- split-expand: fp32 [rows][K] -> bf16 [rows][3K] ---------------
// MODE 0 (activations): segs (hi, hi, lo).  MODE 1 (weights): segs (hi, lo, hi).
template<int MODE>
__global__ __launch_bounds__(256)
void split3(const float* __restrict__ src, const int* __restrict__ gidx,
            __nv_bfloat16* __restrict__ dst, int n4, int Kdiv4)
{
    int i = blockIdx.x * 256 + threadIdx.x;
    if (i >= n4) return;
    int row = i / Kdiv4;
    int c4  = i - row * Kdiv4;
    int K   = Kdiv4 * 4;
    const float* sp = gidx ? (src + (size_t)gidx[row] * K) : (src + (size_t)row * K);
    float4 v = *(const float4*)(sp + c4 * 4);
    __nv_bfloat16 h0 = __float2bfloat16(v.x), h1 = __float2bfloat16(v.y);
    __nv_bfloat16 h2 = __float2bfloat16(v.z), h3 = __float2bfloat16(v.w);
    __nv_bfloat16 l0 = __float2bfloat16(v.x - __bfloat162float(h0));
    __nv_bfloat16 l1 = __float2bfloat16(v.y - __bfloat162float(h1));
    __nv_bfloat16 l2 = __float2bfloat16(v.z - __bfloat162float(h2));
    __nv_bfloat16 l3 = __float2bfloat16(v.w - __bfloat162float(h3));
    __nv_bfloat162 hA(h0, h1), hB(h2, h3), lA(l0, l1), lB(l2, l3);
    size_t base = (size_t)row * (3 * K) + c4 * 4;
    __nv_bfloat162* d0 = (__nv_bfloat162*)(dst + base);
    __nv_bfloat162* d1 = (__nv_bfloat162*)(dst + base + K);
    __nv_bfloat162* d2 = (__nv_bfloat162*)(dst + base + 2 * K);
    d0[0] = hA; d0[1] = hB;
    if (MODE == 0) { d1[0] = hA; d1[1] = hB; d2[0] = lA; d2[1] = lB; }
    else           { d1[0] = lA; d1[1] = lB; d2[0] = hA; d2[1] = hB; }
}

// ---------------- generic HMMA GEMM (mma.sync bf16) ----------------------------
#define HM_BK      32
#define HM_STAGE_B 16384
#define HM_SMEM    (3 * HM_STAGE_B)     // 49152

__device__ __forceinline__ void hm_fill(uint32_t st, const __nv_bfloat16* a,
                                        const __nv_bfloat16* b, int tid, int Kexp)
{
#pragma unroll
    for (int i = tid; i < 512; i += 256) {
        int r = i >> 2, c = i & 3;
        uint32_t dst = st + r * 64 + ((c ^ ((r >> 1) & 3)) << 4);
        cpa16(dst, a + (size_t)r * Kexp + c * 8);
    }
#pragma unroll
    for (int i = tid; i < 512; i += 256) {
        int r = i >> 2, c = i & 3;
        uint32_t dst = st + 8192 + r * 64 + ((c ^ ((r >> 1) & 3)) << 4);
        cpa16(dst, b + (size_t)r * Kexp + c * 8);
    }
    cpa_commit();
}

template<bool REMAP, bool BIAS2>
__global__ __launch_bounds__(256, 2)
void hmma_tn(const __nv_bfloat16* __restrict__ A2, const __nv_bfloat16* __restrict__ B2,
             const float* __restrict__ bias1, const float* __restrict__ bias2,
             float* __restrict__ C, int Kexp, int N)
{
    extern __shared__ char smem[];
    const uint32_t sbase = smem_u32(smem);
    const int tid = threadIdx.x, wid = tid >> 5, lane = tid & 31;
    const int warp_m = wid & 1, warp_n = wid >> 1;
    const int m0 = blockIdx.x * 128;
    const int n0 = blockIdx.y * 128;

    const __nv_bfloat16* aG = A2 + (size_t)m0 * Kexp;
    const __nv_bfloat16* bG = B2 + (size_t)n0 * Kexp;

    uint32_t aoff[4][2], boff[2][2];
#pragma unroll
    for (int mi = 0; mi < 4; ++mi)
#pragma unroll
        for (int ks = 0; ks < 2; ++ks) {
            int row = warp_m * 64 + mi * 16 + (lane & 15);
            int ch  = ks * 2 + (lane >> 4);
            aoff[mi][ks] = row * 64 + ((ch ^ ((row >> 1) & 3)) << 4);
        }
#pragma unroll
    for (int bi = 0; bi < 2; ++bi)
#pragma unroll
        for (int ks = 0; ks < 2; ++ks) {
            int row = warp_n * 32 + bi * 16 + (lane & 7) + ((lane >> 4) << 3);
            int ch  = ks * 2 + ((lane >> 3) & 1);
            boff[bi][ks] = 8192 + row * 64 + ((ch ^ ((row >> 1) & 3)) << 4);
        }

    float acc[4][4][4];
#pragma unroll
    for (int i = 0; i < 4; i++)
#pragma unroll
        for (int j = 0; j < 4; j++)
#pragma unroll
            for (int e = 0; e < 4; e++) acc[i][j][e] = 0.f;

    const int NKB = Kexp / HM_BK;
    hm_fill(sbase,              aG,         bG,         tid, Kexp);
    hm_fill(sbase + HM_STAGE_B, aG + HM_BK, bG + HM_BK, tid, Kexp);

    for (int kb = 0; kb < NKB; ++kb) {
        const int s = kb % 3;
        cpa_wait<1>();
        __syncthreads();
        if (kb + 2 < NKB)
            hm_fill(sbase + ((kb + 2) % 3) * HM_STAGE_B,
                    aG + (size_t)(kb + 2) * HM_BK, bG + (size_t)(kb + 2) * HM_BK, tid, Kexp);

        const uint32_t sb = sbase + s * HM_STAGE_B;
#pragma unroll
        for (int ks = 0; ks < 2; ++ks) {
            uint32_t a[4][4], b[2][4];
#pragma unroll
            for (int mi = 0; mi < 4; ++mi)
                ldsm4(a[mi][0], a[mi][1], a[mi][2], a[mi][3], sb + aoff[mi][ks]);
#pragma unroll
            for (int bi = 0; bi < 2; ++bi)
                ldsm4(b[bi][0], b[bi][1], b[bi][2], b[bi][3], sb + boff[bi][ks]);
#pragma unroll
            for (int mi = 0; mi < 4; ++mi)
#pragma unroll
                for (int ni = 0; ni < 4; ++ni)
                    mma_bf16(acc[mi][ni], a[mi], &b[ni >> 1][(ni & 1) * 2]);
        }
        __syncthreads();
    }

#pragma unroll
    for (int mi = 0; mi < 4; ++mi) {
        int gm = m0 + warp_m * 64 + mi * 16 + (lane >> 2);
        size_t r0 = REMAP ? (size_t)((gm & (T_SEQ - 1)) * BB + (gm >> 9)) : (size_t)gm;
        int gm8 = gm + 8;
        size_t r1 = REMAP ? (size_t)((gm8 & (T_SEQ - 1)) * BB + (gm8 >> 9)) : (size_t)gm8;
#pragma unroll
        for (int ni = 0; ni < 4; ++ni) {
            int col = n0 + warp_n * 32 + ni * 8 + (lane & 3) * 2;
            float2 bv = *(const float2*)(bias1 + col);
            if (BIAS2) {
                float2 b2v = *(const float2*)(bias2 + col);
                bv.x += b2v.x; bv.y += b2v.y;
            }
            float2 v0; v0.x = acc[mi][ni][0] + bv.x; v0.y = acc[mi][ni][1] + bv.y;
            float2 v1; v1.x = acc[mi][ni][2] + bv.x; v1.y = acc[mi][ni][3] + bv.y;
            *(float2*)(C + r0 * (size_t)N + col) = v0;
            *(float2*)(C + r1 * (size_t)N + col) = v1;
        }
    }
}

// ---------------- h0 transpose fill + flag reset -------------------------------
__global__ void fill_h0_kernel(const float* __restrict__ h0)
{
    int i = blockIdx.x * 256 + threadIdx.x;
    if (blockIdx.x == 0 && threadIdx.x < 128) g_flags[threadIdx.x] = 0;
    if (i < BB * HH) {
        int b = i >> 10, j = i & (HH - 1);
        g_hbuf[j * BB + b] = h0[i];
    }
}

// ---------------- persistent LSTM scan (flag barrier, warp-local staging) ------
__device__ __forceinline__ float sigm(float x) { return 1.f / (1.f + expf(-x)); }

__global__ __launch_bounds__(256)
void lstm_scan(const float* __restrict__ xg, const float* __restrict__ Whh,
               const float* __restrict__ c0, float* __restrict__ outSeq,
               float* __restrict__ state_out, int layer)
{
    extern __shared__ float sm[];
    float* ws  = sm;                                  // [1024][32]  128 KB
    float* hs  = sm + HH * 32;                        // [1024][16]   64 KB
    float* red = sm + HH * 32 + HH * 16;              // [32][16][8]  16 KB
    float* xgs = sm + HH * 32 + HH * 16 + 32 * 16 * 8; // [16][4][8]   2 KB
    const uint32_t sb = smem_u32(sm);
    const uint32_t xgs_b = sb + (HH * 32 + HH * 16 + 32 * 16 * 8) * 4;
    const int tid = threadIdx.x, cta = blockIdx.x;
    const int warp = tid >> 5, lane = tid & 31;
    const int rg = lane & 7, bg = lane >> 3;

    // load Whh slice transposed (once; reused for all 512 steps)
    for (int idx = tid; idx < 32 * 256; idx += 256) {
        int r  = idx >> 8;
        int k4 = (idx & 255) * 4;
        int grow = (r >> 3) * HH + cta * 8 + (r & 7);
        float4 w = *(const float4*)(Whh + (size_t)grow * HH + k4);
        ws[(k4 + 0) * 32 + r] = w.x; ws[(k4 + 1) * 32 + r] = w.y;
        ws[(k4 + 2) * 32 + r] = w.z; ws[(k4 + 3) * 32 + r] = w.w;
    }

    const int fb = tid >> 3, fj = tid & 7;
    float c_reg = 0.f;
    if (tid < 128) c_reg = c0[fb * HH + cta * 8 + fj];
    __syncthreads();                                  // ws ready

    int cur = 0;
    const int k0 = warp * 128;
    for (int t = 0; t < T_SEQ; ++t) {
        // xg prefetch for this step (no dependence on h) -> smem via cp.async
        if (tid < 128) {
            int g = (tid & 7) >> 1, half = tid & 1;
            const float* src = xg + (size_t)(t * BB + fb) * G4H + g * HH + cta * 8 + half * 4;
            cpa16(xgs_b + tid * 16, src);
            cpa_commit();
        }

        // wait (acquire) for this warp's 16 source CTAs to finish step t-1
        if (lane < 16) {
            const int* fp = g_flags + warp * 16 + lane;
            while (ld_acq(fp) < t) { }
        }
        __syncwarp();

        // stage own k-slice of h (warp-private region of hs)
        {
            const float4* hb4 = (const float4*)(g_hbuf + cur * (HH * BB) + k0 * BB);
            float4* hs4 = (float4*)(hs + k0 * BB);
#pragma unroll
            for (int i = 0; i < 16; ++i) {
                int idx = lane + i * 32;              // 0..511
                hs4[idx] = __ldcg(hb4 + idx);
            }
        }
        __syncwarp();

        u64 acc2[4][2];
#pragma unroll
        for (int i = 0; i < 4; i++) { acc2[i][0] = 0ULL; acc2[i][1] = 0ULL; }

#pragma unroll 4
        for (int k = k0; k < k0 + 128; ++k) {
            ulonglong2 hv = *(const ulonglong2*)&hs[k * 16 + bg * 4];
            float4 wv = *(const float4*)&ws[k * 32 + rg * 4];
            u64 w0 = pack2(wv.x), w1 = pack2(wv.y), w2 = pack2(wv.z), w3 = pack2(wv.w);
            ffma2(acc2[0][0], w0, hv.x); ffma2(acc2[0][1], w0, hv.y);
            ffma2(acc2[1][0], w1, hv.x); ffma2(acc2[1][1], w1, hv.y);
            ffma2(acc2[2][0], w2, hv.x); ffma2(acc2[2][1], w2, hv.y);
            ffma2(acc2[3][0], w3, hv.x); ffma2(acc2[3][1], w3, hv.y);
        }
#pragma unroll
        for (int i = 0; i < 4; i++) {
            float2 p0 = unpack2(acc2[i][0]);
            float2 p1 = unpack2(acc2[i][1]);
            float* rp = &red[(((rg * 4 + i) << 4) + bg * 4) * 8 + warp];
            rp[0 * 8] = p0.x; rp[1 * 8] = p0.y; rp[2 * 8] = p1.x; rp[3 * 8] = p1.y;
        }
        cpa_wait<0>();
        __syncthreads();

        if (tid < 128) {
            int jg = cta * 8 + fj;
            float s[4];
#pragma unroll
            for (int g = 0; g < 4; ++g) {
                const float* rp = &red[(((g * 8 + fj) << 4) + fb) * 8];
                float sum = rp[0] + rp[1] + rp[2] + rp[3] + rp[4] + rp[5] + rp[6] + rp[7];
                s[g] = sum + xgs[fb * 32 + g * 8 + fj];
            }
            float ci = sigm(s[0]), cf = sigm(s[1]);
            float cg = tanhf(s[2]), co = sigm(s[3]);
            c_reg = cf * c_reg + ci * cg;
            float hnew = co * tanhf(c_reg);
            outSeq[((size_t)fb * T_SEQ + t) * HH + jg] = hnew;
            g_hbuf[(cur ^ 1) * (HH * BB) + jg * BB + fb] = hnew;
            if (t == T_SEQ - 1 && state_out) {
                state_out[(size_t)layer * BB * HH + fb * HH + jg] = hnew;
                state_out[2 * (size_t)BB * HH + (size_t)layer * BB * HH + fb * HH + jg] = c_reg;
            }
        }
        __threadfence();          // publish h stores (gpu scope)
        __syncthreads();          // all writers fenced before flag store
        if (tid == 0) st_rel(g_flags + cta, t + 1);
        cur ^= 1;
    }
}

// ---------------- launch -------------------------------------------------------
extern "C" void kernel_launch(void* const* d_in, const int* in_sizes, int n_in,
                              void* d_out, int out_size)
{
    const int*   x    = (const int*)  d_in[0];
    const float* h0   = (const float*)d_in[1];
    const float* c0   = (const float*)d_in[2];
    const float* emb  = (const float*)d_in[3];
    const float* Wih0 = (const float*)d_in[4];
    const float* Whh0 = (const float*)d_in[5];
    const float* bih0 = (const float*)d_in[6];
    const float* bhh0 = (const float*)d_in[7];
    const float* Wih1 = (const float*)d_in[8];
    const float* Whh1 = (const float*)d_in[9];
    const float* bih1 = (const float*)d_in[10];
    const float* bhh1 = (const float*)d_in[11];
    const float* Wfc  = (const float*)d_in[12];
    const float* bfc  = (const float*)d_in[13];
    float* out = (float*)d_out;

    float *xg, *o0, *o1;
    cudaGetSymbolAddress((void**)&xg, g_xg);
    cudaGetSymbolAddress((void**)&o0, g_out0);
    cudaGetSymbolAddress((void**)&o1, g_out1);
    __nv_bfloat16 *a2, *b2, *w2;
    cudaGetSymbolAddress((void**)&a2, g_A2);
    cudaGetSymbolAddress((void**)&b2, g_B2);
    cudaGetSymbolAddress((void**)&w2, g_W2);

    float* state_out = ((size_t)out_size >= LOGN + 4 * BB * HH) ? (out + LOGN) : nullptr;

    const int SMEM_SCAN = (HH * 32 + HH * 16 + 32 * 16 * 8 + 16 * 4 * 8) * 4;  // 215,040 B
    cudaFuncSetAttribute(lstm_scan, cudaFuncAttributeMaxDynamicSharedMemorySize, SMEM_SCAN);
    cudaFuncSetAttribute(hmma_tn<true, true>,   cudaFuncAttributeMaxDynamicSharedMemorySize, HM_SMEM);
    cudaFuncSetAttribute(hmma_tn<false, false>, cudaFuncAttributeMaxDynamicSharedMemorySize, HM_SMEM);

    // Wfc split (hi|lo|hi) — biggest split, up front
    split3<1><<<(VV * HH / 4 + 255) / 256, 256>>>(Wfc, nullptr, b2, VV * HH / 4, HH / 4);

    // ---- layer 0: xg0 = gather(emb,x) @ Wih0^T + bih0 + bhh0 (HMMA, Kexp=1536)
    split3<0><<<(M_ROWS * EE / 4 + 255) / 256, 256>>>(emb, x, a2, M_ROWS * EE / 4, EE / 4);
    split3<1><<<(G4H * EE / 4 + 255) / 256, 256>>>(Wih0, nullptr, w2, G4H * EE / 4, EE / 4);
    hmma_tn<true, true><<<dim3(M_ROWS / 128, G4H / 128), 256, HM_SMEM>>>(
        a2, w2, bih0, bhh0, xg, 3 * EE, G4H);
    fill_h0_kernel<<<(BB * HH + 255) / 256, 256>>>(h0);
    lstm_scan<<<128, 256, SMEM_SCAN>>>(xg, Whh0, c0, o0, state_out, 0);

    // ---- layer 1: xg1 = out0 @ Wih1^T + bih1 + bhh1 (HMMA, Kexp=3072)
    split3<0><<<(M_ROWS * HH / 4 + 255) / 256, 256>>>(o0, nullptr, a2, M_ROWS * HH / 4, HH / 4);
    split3<1><<<(G4H * HH / 4 + 255) / 256, 256>>>(Wih1, nullptr, w2, G4H * HH / 4, HH / 4);
    hmma_tn<true, true><<<dim3(M_ROWS / 128, G4H / 128), 256, HM_SMEM>>>(
        a2, w2, bih1, bhh1, xg, 3 * HH, G4H);
    fill_h0_kernel<<<(BB * HH + 255) / 256, 256>>>(h0 + BB * HH);
    lstm_scan<<<128, 256, SMEM_SCAN>>>(xg, Whh1, c0 + BB * HH, o1, state_out, 1);

    // ---- FC: logits = out1 @ Wfc^T + bfc (HMMA, Kexp=3072)
    split3<0><<<(M_ROWS * HH / 4 + 255) / 256, 256>>>(o1, nullptr, a2, M_ROWS * HH / 4, HH / 4);
    hmma_tn<false, false><<<dim3(M_ROWS / 128, VV / 128), 256, HM_SMEM>>>(
        a2, b2, bfc, nullptr, out, 3 * HH, VV);
}

// round 10
// speedup vs baseline: 1.4316x; 1.4316x over previous
#include <cuda_runtime.h>
#include <cuda_bf16.h>
#include <cstdint>

// ---------------- problem constants ----------------
#define T_SEQ 512
#define BB    16
#define HH    1024
#define EE    512
#define VV    32000
#define G4H   4096
#define M_ROWS (BB * T_SEQ)                     // 8192
#define LOGN  ((size_t)M_ROWS * (size_t)VV)     // 262,144,000

// ---------------- device scratch (static globals: allowed) ----------------
__device__ float g_xg[(size_t)T_SEQ * BB * G4H];      // 134 MB, reused per layer
__device__ float g_out0[(size_t)M_ROWS * HH];         // layer-0 h sequence
__device__ float g_out1[(size_t)M_ROWS * HH];         // layer-1 h sequence
__device__ float g_hbuf[2 * HH * BB];                 // double buffer, [j][b] layout
__device__ unsigned g_bar;                            // zero-init
__device__ volatile unsigned g_epoch;                 // zero-init
__device__ __nv_bfloat16 g_A2[(size_t)M_ROWS * 3072]; // 50 MB  activations (hi|hi|lo)
__device__ __nv_bfloat16 g_B2[(size_t)VV * 3072];     // 197 MB Wfc (hi|lo|hi)
__device__ __nv_bfloat16 g_W2[(size_t)G4H * 3072];    // 25 MB  Wih (hi|lo|hi)

// ---------------- f32x2 packed-FMA helpers ----------------
typedef unsigned long long u64;
__device__ __forceinline__ u64 pack2(float v) {
    u64 r; asm("mov.b64 %0, {%1, %1};" : "=l"(r) : "f"(v)); return r;
}
__device__ __forceinline__ void ffma2(u64& c, u64 a, u64 b) {
    asm("fma.rn.f32x2 %0, %1, %2, %0;" : "+l"(c) : "l"(a), "l"(b));
}
__device__ __forceinline__ float2 unpack2(u64 v) {
    float lo, hi; asm("mov.b64 {%0, %1}, %2;" : "=f"(lo), "=f"(hi) : "l"(v));
    float2 f; f.x = lo; f.y = hi; return f;
}

// ---------------- base-ISA async-copy / ldmatrix / mma helpers ----------------
__device__ __forceinline__ uint32_t smem_u32(const void* p) {
    uint32_t a;
    asm("{ .reg .u64 t; cvta.to.shared.u64 t, %1; cvt.u32.u64 %0, t; }" : "=r"(a) : "l"(p));
    return a;
}
__device__ __forceinline__ void cpa16(uint32_t dst, const void* src) {
    asm volatile("cp.async.cg.shared.global [%0], [%1], 16;" :: "r"(dst), "l"(src));
}
__device__ __forceinline__ void cpa_commit() { asm volatile("cp.async.commit_group;" ::: "memory"); }
template<int N> __device__ __forceinline__ void cpa_wait() {
    asm volatile("cp.async.wait_group %0;" :: "n"(N) : "memory");
}
__device__ __forceinline__ void ldsm4(uint32_t& r0, uint32_t& r1, uint32_t& r2, uint32_t& r3,
                                      uint32_t a) {
    asm volatile("ldmatrix.sync.aligned.m8n8.x4.shared.b16 {%0,%1,%2,%3}, [%4];"
                 : "=r"(r0), "=r"(r1), "=r"(r2), "=r"(r3) : "r"(a));
}
__device__ __forceinline__ void mma_bf16(float* c, const uint32_t* a, const uint32_t* b) {
    asm volatile(
        "mma.sync.aligned.m16n8k16.row.col.f32.bf16.bf16.f32 "
        "{%0,%1,%2,%3}, {%4,%5,%6,%7}, {%8,%9}, {%0,%1,%2,%3};"
        : "+f"(c[0]), "+f"(c[1]), "+f"(c[2]), "+f"(c[3])
        : "r"(a[0]), "r"(a[1]), "r"(a[2]), "r"(a[3]), "r"(b[0]), "r"(b[1]));
}

// ---------------- split-expand: fp32 [rows][K] -> bf16 [rows][3K] ---------------
// MODE 0 (activations): segs (hi, hi, lo).  MODE 1 (weights): segs (hi, lo, hi).
template<int MODE>
__global__ __launch_bounds__(256)
void split3(const float* __restrict__ src, const int* __restrict__ gidx,
            __nv_bfloat16* __restrict__ dst, int n4, int Kdiv4)
{
    int i = blockIdx.x * 256 + threadIdx.x;
    if (i >= n4) return;
    int row = i / Kdiv4;
    int c4  = i - row * Kdiv4;
    int K   = Kdiv4 * 4;
    const float* sp = gidx ? (src + (size_t)gidx[row] * K) : (src + (size_t)row * K);
    float4 v = *(const float4*)(sp + c4 * 4);
    __nv_bfloat16 h0 = __float2bfloat16(v.x), h1 = __float2bfloat16(v.y);
    __nv_bfloat16 h2 = __float2bfloat16(v.z), h3 = __float2bfloat16(v.w);
    __nv_bfloat16 l0 = __float2bfloat16(v.x - __bfloat162float(h0));
    __nv_bfloat16 l1 = __float2bfloat16(v.y - __bfloat162float(h1));
    __nv_bfloat16 l2 = __float2bfloat16(v.z - __bfloat162float(h2));
    __nv_bfloat16 l3 = __float2bfloat16(v.w - __bfloat162float(h3));
    __nv_bfloat162 hA(h0, h1), hB(h2, h3), lA(l0, l1), lB(l2, l3);
    size_t base = (size_t)row * (3 * K) + c4 * 4;
    __nv_bfloat162* d0 = (__nv_bfloat162*)(dst + base);
    __nv_bfloat162* d1 = (__nv_bfloat162*)(dst + base + K);
    __nv_bfloat162* d2 = (__nv_bfloat162*)(dst + base + 2 * K);
    d0[0] = hA; d0[1] = hB;
    if (MODE == 0) { d1[0] = hA; d1[1] = hB; d2[0] = lA; d2[1] = lB; }
    else           { d1[0] = lA; d1[1] = lB; d2[0] = hA; d2[1] = hB; }
}

// ---------------- generic HMMA GEMM (mma.sync bf16) ----------------------------
#define HM_BK      32
#define HM_STAGE_B 16384
#define HM_SMEM    (3 * HM_STAGE_B)     // 49152

__device__ __forceinline__ void hm_fill(uint32_t st, const __nv_bfloat16* a,
                                        const __nv_bfloat16* b, int tid, int Kexp)
{
#pragma unroll
    for (int i = tid; i < 512; i += 256) {
        int r = i >> 2, c = i & 3;
        uint32_t dst = st + r * 64 + ((c ^ ((r >> 1) & 3)) << 4);
        cpa16(dst, a + (size_t)r * Kexp + c * 8);
    }
#pragma unroll
    for (int i = tid; i < 512; i += 256) {
        int r = i >> 2, c = i & 3;
        uint32_t dst = st + 8192 + r * 64 + ((c ^ ((r >> 1) & 3)) << 4);
        cpa16(dst, b + (size_t)r * Kexp + c * 8);
    }
    cpa_commit();
}

template<bool REMAP, bool BIAS2>
__global__ __launch_bounds__(256, 2)
void hmma_tn(const __nv_bfloat16* __restrict__ A2, const __nv_bfloat16* __restrict__ B2,
             const float* __restrict__ bias1, const float* __restrict__ bias2,
             float* __restrict__ C, int Kexp, int N)
{
    extern __shared__ char smem[];
    const uint32_t sbase = smem_u32(smem);
    const int tid = threadIdx.x, wid = tid >> 5, lane = tid & 31;
    const int warp_m = wid & 1, warp_n = wid >> 1;
    const int m0 = blockIdx.x * 128;
    const int n0 = blockIdx.y * 128;

    const __nv_bfloat16* aG = A2 + (size_t)m0 * Kexp;
    const __nv_bfloat16* bG = B2 + (size_t)n0 * Kexp;

    uint32_t aoff[4][2], boff[2][2];
#pragma unroll
    for (int mi = 0; mi < 4; ++mi)
#pragma unroll
        for (int ks = 0; ks < 2; ++ks) {
            int row = warp_m * 64 + mi * 16 + (lane & 15);
            int ch  = ks * 2 + (lane >> 4);
            aoff[mi][ks] = row * 64 + ((ch ^ ((row >> 1) & 3)) << 4);
        }
#pragma unroll
    for (int bi = 0; bi < 2; ++bi)
#pragma unroll
        for (int ks = 0; ks < 2; ++ks) {
            int row = warp_n * 32 + bi * 16 + (lane & 7) + ((lane >> 4) << 3);
            int ch  = ks * 2 + ((lane >> 3) & 1);
            boff[bi][ks] = 8192 + row * 64 + ((ch ^ ((row >> 1) & 3)) << 4);
        }

    float acc[4][4][4];
#pragma unroll
    for (int i = 0; i < 4; i++)
#pragma unroll
        for (int j = 0; j < 4; j++)
#pragma unroll
            for (int e = 0; e < 4; e++) acc[i][j][e] = 0.f;

    const int NKB = Kexp / HM_BK;
    hm_fill(sbase,              aG,         bG,         tid, Kexp);
    hm_fill(sbase + HM_STAGE_B, aG + HM_BK, bG + HM_BK, tid, Kexp);

    for (int kb = 0; kb < NKB; ++kb) {
        const int s = kb % 3;
        cpa_wait<1>();
        __syncthreads();
        if (kb + 2 < NKB)
            hm_fill(sbase + ((kb + 2) % 3) * HM_STAGE_B,
                    aG + (size_t)(kb + 2) * HM_BK, bG + (size_t)(kb + 2) * HM_BK, tid, Kexp);

        const uint32_t sb = sbase + s * HM_STAGE_B;
#pragma unroll
        for (int ks = 0; ks < 2; ++ks) {
            uint32_t a[4][4], b[2][4];
#pragma unroll
            for (int mi = 0; mi < 4; ++mi)
                ldsm4(a[mi][0], a[mi][1], a[mi][2], a[mi][3], sb + aoff[mi][ks]);
#pragma unroll
            for (int bi = 0; bi < 2; ++bi)
                ldsm4(b[bi][0], b[bi][1], b[bi][2], b[bi][3], sb + boff[bi][ks]);
#pragma unroll
            for (int mi = 0; mi < 4; ++mi)
#pragma unroll
                for (int ni = 0; ni < 4; ++ni)
                    mma_bf16(acc[mi][ni], a[mi], &b[ni >> 1][(ni & 1) * 2]);
        }
        __syncthreads();
    }

#pragma unroll
    for (int mi = 0; mi < 4; ++mi) {
        int gm = m0 + warp_m * 64 + mi * 16 + (lane >> 2);
        size_t r0 = REMAP ? (size_t)((gm & (T_SEQ - 1)) * BB + (gm >> 9)) : (size_t)gm;
        int gm8 = gm + 8;
        size_t r1 = REMAP ? (size_t)((gm8 & (T_SEQ - 1)) * BB + (gm8 >> 9)) : (size_t)gm8;
#pragma unroll
        for (int ni = 0; ni < 4; ++ni) {
            int col = n0 + warp_n * 32 + ni * 8 + (lane & 3) * 2;
            float2 bv = *(const float2*)(bias1 + col);
            if (BIAS2) {
                float2 b2v = *(const float2*)(bias2 + col);
                bv.x += b2v.x; bv.y += b2v.y;
            }
            float2 v0; v0.x = acc[mi][ni][0] + bv.x; v0.y = acc[mi][ni][1] + bv.y;
            float2 v1; v1.x = acc[mi][ni][2] + bv.x; v1.y = acc[mi][ni][3] + bv.y;
            *(float2*)(C + r0 * (size_t)N + col) = v0;
            *(float2*)(C + r1 * (size_t)N + col) = v1;
        }
    }
}

// ---------------- h0 transpose fill: g_hbuf[0][j*16+b] = h0[b][j] --------------
__global__ void fill_h0_kernel(const float* __restrict__ h0)
{
    int i = blockIdx.x * 256 + threadIdx.x;
    if (i < BB * HH) {
        int b = i >> 10, j = i & (HH - 1);
        g_hbuf[j * BB + b] = h0[i];
    }
}

// ---------------- persistent LSTM scan (R5 barrier + warp staging + prefetch) --
__device__ __forceinline__ float sigm(float x) { return 1.f / (1.f + expf(-x)); }

__global__ __launch_bounds__(256)
void lstm_scan(const float* __restrict__ xg, const float* __restrict__ Whh,
               const float* __restrict__ c0, float* __restrict__ outSeq,
               float* __restrict__ state_out, int layer)
{
    extern __shared__ float sm[];
    float* ws  = sm;                                   // [1024][32]  128 KB
    float* hs  = sm + HH * 32;                         // [1024][16]   64 KB
    float* red = sm + HH * 32 + HH * 16;               // [32][16][8]  16 KB
    float* xgs = sm + HH * 32 + HH * 16 + 32 * 16 * 8; // [16][4][8]    2 KB
    const uint32_t sbm = smem_u32(sm);
    const uint32_t xgs_b = sbm + (HH * 32 + HH * 16 + 32 * 16 * 8) * 4;
    const int tid = threadIdx.x, cta = blockIdx.x;
    const int warp = tid >> 5, lane = tid & 31;
    const int rg = lane & 7, bg = lane >> 3;

    // load Whh slice transposed (once; reused for all 512 steps)
    for (int idx = tid; idx < 32 * 256; idx += 256) {
        int r  = idx >> 8;
        int k4 = (idx & 255) * 4;
        int grow = (r >> 3) * HH + cta * 8 + (r & 7);
        float4 w = *(const float4*)(Whh + (size_t)grow * HH + k4);
        ws[(k4 + 0) * 32 + r] = w.x; ws[(k4 + 1) * 32 + r] = w.y;
        ws[(k4 + 2) * 32 + r] = w.z; ws[(k4 + 3) * 32 + r] = w.w;
    }

    const int fb = tid >> 3, fj = tid & 7;
    float c_reg = 0.f;
    if (tid < 128) c_reg = c0[fb * HH + cta * 8 + fj];
    __syncthreads();                                   // ws ready

    int cur = 0;
    const int k0 = warp * 128;
    for (int t = 0; t < T_SEQ; ++t) {
        // xg prefetch for this step (independent of h; hides under stage+k-loop)
        if (tid < 128) {
            int g = (tid & 7) >> 1, half = tid & 1;
            cpa16(xgs_b + tid * 16,
                  xg + (size_t)(t * BB + fb) * G4H + g * HH + cta * 8 + half * 4);
            cpa_commit();
        }

        // stage own k-slice of h (warp-private region; safe after prev barrier)
        {
            const float4* hb4 = (const float4*)(g_hbuf + cur * (HH * BB) + k0 * BB);
            float4* hs4 = (float4*)(hs + k0 * BB);
            hs4[lane]      = __ldcg(hb4 + lane);
            hs4[lane + 32] = __ldcg(hb4 + lane + 32);
            hs4[lane + 64] = __ldcg(hb4 + lane + 64);
            hs4[lane + 96] = __ldcg(hb4 + lane + 96);
            hs4[lane + 128] = __ldcg(hb4 + lane + 128);
            hs4[lane + 160] = __ldcg(hb4 + lane + 160);
            hs4[lane + 192] = __ldcg(hb4 + lane + 192);
            hs4[lane + 224] = __ldcg(hb4 + lane + 224);
            hs4[lane + 256] = __ldcg(hb4 + lane + 256);
            hs4[lane + 288] = __ldcg(hb4 + lane + 288);
            hs4[lane + 320] = __ldcg(hb4 + lane + 320);
            hs4[lane + 352] = __ldcg(hb4 + lane + 352);
            hs4[lane + 384] = __ldcg(hb4 + lane + 384);
            hs4[lane + 416] = __ldcg(hb4 + lane + 416);
            hs4[lane + 448] = __ldcg(hb4 + lane + 448);
            hs4[lane + 480] = __ldcg(hb4 + lane + 480);
        }
        __syncwarp();

        u64 acc2[4][2];
#pragma unroll
        for (int i = 0; i < 4; i++) { acc2[i][0] = 0ULL; acc2[i][1] = 0ULL; }

#pragma unroll 4
        for (int k = k0; k < k0 + 128; ++k) {
            ulonglong2 hv = *(const ulonglong2*)&hs[k * 16 + bg * 4];
            float4 wv = *(const float4*)&ws[k * 32 + rg * 4];
            u64 w0 = pack2(wv.x), w1 = pack2(wv.y), w2 = pack2(wv.z), w3 = pack2(wv.w);
            ffma2(acc2[0][0], w0, hv.x); ffma2(acc2[0][1], w0, hv.y);
            ffma2(acc2[1][0], w1, hv.x); ffma2(acc2[1][1], w1, hv.y);
            ffma2(acc2[2][0], w2, hv.x); ffma2(acc2[2][1], w2, hv.y);
            ffma2(acc2[3][0], w3, hv.x); ffma2(acc2[3][1], w3, hv.y);
        }
#pragma unroll
        for (int i = 0; i < 4; i++) {
            float2 p0 = unpack2(acc2[i][0]);
            float2 p1 = unpack2(acc2[i][1]);
            float* rp = &red[(((rg * 4 + i) << 4) + bg * 4) * 8 + warp];
            rp[0 * 8] = p0.x; rp[1 * 8] = p0.y; rp[2 * 8] = p1.x; rp[3 * 8] = p1.y;
        }
        cpa_wait<0>();            // xg prefetch complete
        __syncthreads();

        if (tid < 128) {
            int jg = cta * 8 + fj;
            float s[4];
#pragma unroll
            for (int g = 0; g < 4; ++g) {
                const float* rp = &red[(((g * 8 + fj) << 4) + fb) * 8];
                float sum = rp[0] + rp[1] + rp[2] + rp[3] + rp[4] + rp[5] + rp[6] + rp[7];
                s[g] = sum + xgs[fb * 32 + g * 8 + fj];
            }
            float ci = sigm(s[0]), cf = sigm(s[1]);
            float cg = tanhf(s[2]), co = sigm(s[3]);
            c_reg = cf * c_reg + ci * cg;
            float hnew = co * tanhf(c_reg);
            outSeq[((size_t)fb * T_SEQ + t) * HH + jg] = hnew;
            g_hbuf[(cur ^ 1) * (HH * BB) + jg * BB + fb] = hnew;
            if (t == T_SEQ - 1 && state_out) {
                state_out[(size_t)layer * BB * HH + fb * HH + jg] = hnew;
                state_out[2 * (size_t)BB * HH + (size_t)layer * BB * HH + fb * HH + jg] = c_reg;
            }
        }

        // ---- R5 grid barrier (sense-reversal; validated twice) ----
        __syncthreads();
        if (tid == 0) {
            unsigned e = g_epoch;
            __threadfence();
            if (atomicAdd(&g_bar, 1u) == (unsigned)gridDim.x - 1u) {
                g_bar = 0;
                __threadfence();
                g_epoch = e + 1;
            } else {
                while (g_epoch == e) { }
            }
        }
        __syncthreads();
        cur ^= 1;
    }
}

// ---------------- launch -------------------------------------------------------
extern "C" void kernel_launch(void* const* d_in, const int* in_sizes, int n_in,
                              void* d_out, int out_size)
{
    const int*   x    = (const int*)  d_in[0];
    const float* h0   = (const float*)d_in[1];
    const float* c0   = (const float*)d_in[2];
    const float* emb  = (const float*)d_in[3];
    const float* Wih0 = (const float*)d_in[4];
    const float* Whh0 = (const float*)d_in[5];
    const float* bih0 = (const float*)d_in[6];
    const float* bhh0 = (const float*)d_in[7];
    const float* Wih1 = (const float*)d_in[8];
    const float* Whh1 = (const float*)d_in[9];
    const float* bih1 = (const float*)d_in[10];
    const float* bhh1 = (const float*)d_in[11];
    const float* Wfc  = (const float*)d_in[12];
    const float* bfc  = (const float*)d_in[13];
    float* out = (float*)d_out;

    float *xg, *o0, *o1;
    cudaGetSymbolAddress((void**)&xg, g_xg);
    cudaGetSymbolAddress((void**)&o0, g_out0);
    cudaGetSymbolAddress((void**)&o1, g_out1);
    __nv_bfloat16 *a2, *b2, *w2;
    cudaGetSymbolAddress((void**)&a2, g_A2);
    cudaGetSymbolAddress((void**)&b2, g_B2);
    cudaGetSymbolAddress((void**)&w2, g_W2);

    float* state_out = ((size_t)out_size >= LOGN + 4 * BB * HH) ? (out + LOGN) : nullptr;

    const int SMEM_SCAN = (HH * 32 + HH * 16 + 32 * 16 * 8 + 16 * 4 * 8) * 4;  // 215,040 B
    cudaFuncSetAttribute(lstm_scan, cudaFuncAttributeMaxDynamicSharedMemorySize, SMEM_SCAN);
    cudaFuncSetAttribute(hmma_tn<true, true>,   cudaFuncAttributeMaxDynamicSharedMemorySize, HM_SMEM);
    cudaFuncSetAttribute(hmma_tn<false, false>, cudaFuncAttributeMaxDynamicSharedMemorySize, HM_SMEM);

    // Wfc split (hi|lo|hi) — biggest split, up front
    split3<1><<<(VV * HH / 4 + 255) / 256, 256>>>(Wfc, nullptr, b2, VV * HH / 4, HH / 4);

    // ---- layer 0: xg0 = gather(emb,x) @ Wih0^T + bih0 + bhh0 (HMMA, Kexp=1536)
    split3<0><<<(M_ROWS * EE / 4 + 255) / 256, 256>>>(emb, x, a2, M_ROWS * EE / 4, EE / 4);
    split3<1><<<(G4H * EE / 4 + 255) / 256, 256>>>(Wih0, nullptr, w2, G4H * EE / 4, EE / 4);
    hmma_tn<true, true><<<dim3(M_ROWS / 128, G4H / 128), 256, HM_SMEM>>>(
        a2, w2, bih0, bhh0, xg, 3 * EE, G4H);
    fill_h0_kernel<<<(BB * HH + 255) / 256, 256>>>(h0);
    lstm_scan<<<128, 256, SMEM_SCAN>>>(xg, Whh0, c0, o0, state_out, 0);

    // ---- layer 1: xg1 = out0 @ Wih1^T + bih1 + bhh1 (HMMA, Kexp=3072)
    split3<0><<<(M_ROWS * HH / 4 + 255) / 256, 256>>>(o0, nullptr, a2, M_ROWS * HH / 4, HH / 4);
    split3<1><<<(G4H * HH / 4 + 255) / 256, 256>>>(Wih1, nullptr, w2, G4H * HH / 4, HH / 4);
    hmma_tn<true, true><<<dim3(M_ROWS / 128, G4H / 128), 256, HM_SMEM>>>(
        a2, w2, bih1, bhh1, xg, 3 * HH, G4H);
    fill_h0_kernel<<<(BB * HH + 255) / 256, 256>>>(h0 + BB * HH);
    lstm_scan<<<128, 256, SMEM_SCAN>>>(xg, Whh1, c0 + BB * HH, o1, state_out, 1);

    // ---- FC: logits = out1 @ Wfc^T + bfc (HMMA, Kexp=3072)
    split3<0><<<(M_ROWS * HH / 4 + 255) / 256, 256>>>(o1, nullptr, a2, M_ROWS * HH / 4, HH / 4);
    hmma_tn<false, false><<<dim3(M_ROWS / 128, VV / 128), 256, HM_SMEM>>>(
        a2, b2, bfc, nullptr, out, 3 * HH, VV);
}

// round 12
// speedup vs baseline: 1.4469x; 1.0107x over previous
#include <cuda_runtime.h>
#include <cuda_bf16.h>
#include <cstdint>

// ---------------- problem constants ----------------
#define T_SEQ 512
#define BB    16
#define HH    1024
#define EE    512
#define VV    32000
#define G4H   4096
#define M_ROWS (BB * T_SEQ)                     // 8192
#define LOGN  ((size_t)M_ROWS * (size_t)VV)     // 262,144,000

// ---------------- device scratch (static globals: allowed) ----------------
__device__ float g_xg[(size_t)T_SEQ * BB * G4H];      // 134 MB, reused per layer
__device__ float g_out0[(size_t)M_ROWS * HH];         // layer-0 h sequence
__device__ float g_out1[(size_t)M_ROWS * HH];         // layer-1 h sequence
__device__ float g_hbuf[2 * HH * BB];                 // double buffer, [j][b] layout
__device__ unsigned g_bar1[8 * 32];                   // group counters, 128B apart
__device__ unsigned g_bar2;                           // super counter
__device__ volatile unsigned g_epoch;                 // zero-init
__device__ __nv_bfloat16 g_A2[(size_t)M_ROWS * 3072]; // 50 MB  activations (hi|hi|lo)
__device__ __nv_bfloat16 g_B2[(size_t)VV * 3072];     // 197 MB Wfc (hi|lo|hi)
__device__ __nv_bfloat16 g_W2[(size_t)G4H * 3072];    // 25 MB  Wih (hi|lo|hi)

// ---------------- f32x2 packed-FMA helpers ----------------
typedef unsigned long long u64;
__device__ __forceinline__ u64 pack2(float v) {
    u64 r; asm("mov.b64 %0, {%1, %1};" : "=l"(r) : "f"(v)); return r;
}
__device__ __forceinline__ void ffma2(u64& c, u64 a, u64 b) {
    asm("fma.rn.f32x2 %0, %1, %2, %0;" : "+l"(c) : "l"(a), "l"(b));
}
__device__ __forceinline__ float2 unpack2(u64 v) {
    float lo, hi; asm("mov.b64 {%0, %1}, %2;" : "=f"(lo), "=f"(hi) : "l"(v));
    float2 f; f.x = lo; f.y = hi; return f;
}

// ---------------- base-ISA async-copy / ldmatrix / mma helpers ----------------
__device__ __forceinline__ uint32_t smem_u32(const void* p) {
    uint32_t a;
    asm("{ .reg .u64 t; cvta.to.shared.u64 t, %1; cvt.u32.u64 %0, t; }" : "=r"(a) : "l"(p));
    return a;
}
__device__ __forceinline__ void cpa16(uint32_t dst, const void* src) {
    asm volatile("cp.async.cg.shared.global [%0], [%1], 16;" :: "r"(dst), "l"(src));
}
__device__ __forceinline__ void cpa_commit() { asm volatile("cp.async.commit_group;" ::: "memory"); }
template<int N> __device__ __forceinline__ void cpa_wait() {
    asm volatile("cp.async.wait_group %0;" :: "n"(N) : "memory");
}
__device__ __forceinline__ void ldsm4(uint32_t& r0, uint32_t& r1, uint32_t& r2, uint32_t& r3,
                                      uint32_t a) {
    asm volatile("ldmatrix.sync.aligned.m8n8.x4.shared.b16 {%0,%1,%2,%3}, [%4];"
                 : "=r"(r0), "=r"(r1), "=r"(r2), "=r"(r3) : "r"(a));
}
__device__ __forceinline__ void mma_bf16(float* c, const uint32_t* a, const uint32_t* b) {
    asm volatile(
        "mma.sync.aligned.m16n8k16.row.col.f32.bf16.bf16.f32 "
        "{%0,%1,%2,%3}, {%4,%5,%6,%7}, {%8,%9}, {%0,%1,%2,%3};"
        : "+f"(c[0]), "+f"(c[1]), "+f"(c[2]), "+f"(c[3])
        : "r"(a[0]), "r"(a[1]), "r"(a[2]), "r"(a[3]), "r"(b[0]), "r"(b[1]));
}

// ---------------- split-expand: fp32 [rows][K] -> bf16 [rows][3K] ---------------
// MODE 0 (activations): segs (hi, hi, lo).  MODE 1 (weights): segs (hi, lo, hi).
template<int MODE>
__global__ __launch_bounds__(256)
void split3(const float* __restrict__ src, const int* __restrict__ gidx,
            __nv_bfloat16* __restrict__ dst, int n4, int Kdiv4)
{
    int i = blockIdx.x * 256 + threadIdx.x;
    if (i >= n4) return;
    int row = i / Kdiv4;
    int c4  = i - row * Kdiv4;
    int K   = Kdiv4 * 4;
    const float* sp = gidx ? (src + (size_t)gidx[row] * K) : (src + (size_t)row * K);
    float4 v = *(const float4*)(sp + c4 * 4);
    __nv_bfloat16 h0 = __float2bfloat16(v.x), h1 = __float2bfloat16(v.y);
    __nv_bfloat16 h2 = __float2bfloat16(v.z), h3 = __float2bfloat16(v.w);
    __nv_bfloat16 l0 = __float2bfloat16(v.x - __bfloat162float(h0));
    __nv_bfloat16 l1 = __float2bfloat16(v.y - __bfloat162float(h1));
    __nv_bfloat16 l2 = __float2bfloat16(v.z - __bfloat162float(h2));
    __nv_bfloat16 l3 = __float2bfloat16(v.w - __bfloat162float(h3));
    __nv_bfloat162 hA(h0, h1), hB(h2, h3), lA(l0, l1), lB(l2, l3);
    size_t base = (size_t)row * (3 * K) + c4 * 4;
    __nv_bfloat162* d0 = (__nv_bfloat162*)(dst + base);
    __nv_bfloat162* d1 = (__nv_bfloat162*)(dst + base + K);
    __nv_bfloat162* d2 = (__nv_bfloat162*)(dst + base + 2 * K);
    d0[0] = hA; d0[1] = hB;
    if (MODE == 0) { d1[0] = hA; d1[1] = hB; d2[0] = lA; d2[1] = lB; }
    else           { d1[0] = lA; d1[1] = lB; d2[0] = hA; d2[1] = hB; }
}

// ---------------- generic HMMA GEMM (mma.sync bf16) ----------------------------
#define HM_BK      32
#define HM_STAGE_B 16384
#define HM_SMEM    (3 * HM_STAGE_B)     // 49152

__device__ __forceinline__ void hm_fill(uint32_t st, const __nv_bfloat16* a,
                                        const __nv_bfloat16* b, int tid, int Kexp)
{
#pragma unroll
    for (int i = tid; i < 512; i += 256) {
        int r = i >> 2, c = i & 3;
        uint32_t dst = st + r * 64 + ((c ^ ((r >> 1) & 3)) << 4);
        cpa16(dst, a + (size_t)r * Kexp + c * 8);
    }
#pragma unroll
    for (int i = tid; i < 512; i += 256) {
        int r = i >> 2, c = i & 3;
        uint32_t dst = st + 8192 + r * 64 + ((c ^ ((r >> 1) & 3)) << 4);
        cpa16(dst, b + (size_t)r * Kexp + c * 8);
    }
    cpa_commit();
}

template<bool REMAP, bool BIAS2>
__global__ __launch_bounds__(256, 2)
void hmma_tn(const __nv_bfloat16* __restrict__ A2, const __nv_bfloat16* __restrict__ B2,
             const float* __restrict__ bias1, const float* __restrict__ bias2,
             float* __restrict__ C, int Kexp, int N)
{
    extern __shared__ char smem[];
    const uint32_t sbase = smem_u32(smem);
    const int tid = threadIdx.x, wid = tid >> 5, lane = tid & 31;
    const int warp_m = wid & 1, warp_n = wid >> 1;
    const int m0 = blockIdx.x * 128;
    const int n0 = blockIdx.y * 128;

    const __nv_bfloat16* aG = A2 + (size_t)m0 * Kexp;
    const __nv_bfloat16* bG = B2 + (size_t)n0 * Kexp;

    uint32_t aoff[4][2], boff[2][2];
#pragma unroll
    for (int mi = 0; mi < 4; ++mi)
#pragma unroll
        for (int ks = 0; ks < 2; ++ks) {
            int row = warp_m * 64 + mi * 16 + (lane & 15);
            int ch  = ks * 2 + (lane >> 4);
            aoff[mi][ks] = row * 64 + ((ch ^ ((row >> 1) & 3)) << 4);
        }
#pragma unroll
    for (int bi = 0; bi < 2; ++bi)
#pragma unroll
        for (int ks = 0; ks < 2; ++ks) {
            int row = warp_n * 32 + bi * 16 + (lane & 7) + ((lane >> 4) << 3);
            int ch  = ks * 2 + ((lane >> 3) & 1);
            boff[bi][ks] = 8192 + row * 64 + ((ch ^ ((row >> 1) & 3)) << 4);
        }

    float acc[4][4][4];
#pragma unroll
    for (int i = 0; i < 4; i++)
#pragma unroll
        for (int j = 0; j < 4; j++)
#pragma unroll
            for (int e = 0; e < 4; e++) acc[i][j][e] = 0.f;

    const int NKB = Kexp / HM_BK;
    hm_fill(sbase,              aG,         bG,         tid, Kexp);
    hm_fill(sbase + HM_STAGE_B, aG + HM_BK, bG + HM_BK, tid, Kexp);

    for (int kb = 0; kb < NKB; ++kb) {
        const int s = kb % 3;
        cpa_wait<1>();
        __syncthreads();
        if (kb + 2 < NKB)
            hm_fill(sbase + ((kb + 2) % 3) * HM_STAGE_B,
                    aG + (size_t)(kb + 2) * HM_BK, bG + (size_t)(kb + 2) * HM_BK, tid, Kexp);

        const uint32_t sb = sbase + s * HM_STAGE_B;
#pragma unroll
        for (int ks = 0; ks < 2; ++ks) {
            uint32_t a[4][4], b[2][4];
#pragma unroll
            for (int mi = 0; mi < 4; ++mi)
                ldsm4(a[mi][0], a[mi][1], a[mi][2], a[mi][3], sb + aoff[mi][ks]);
#pragma unroll
            for (int bi = 0; bi < 2; ++bi)
                ldsm4(b[bi][0], b[bi][1], b[bi][2], b[bi][3], sb + boff[bi][ks]);
#pragma unroll
            for (int mi = 0; mi < 4; ++mi)
#pragma unroll
                for (int ni = 0; ni < 4; ++ni)
                    mma_bf16(acc[mi][ni], a[mi], &b[ni >> 1][(ni & 1) * 2]);
        }
        __syncthreads();
    }

#pragma unroll
    for (int mi = 0; mi < 4; ++mi) {
        int gm = m0 + warp_m * 64 + mi * 16 + (lane >> 2);
        size_t r0 = REMAP ? (size_t)((gm & (T_SEQ - 1)) * BB + (gm >> 9)) : (size_t)gm;
        int gm8 = gm + 8;
        size_t r1 = REMAP ? (size_t)((gm8 & (T_SEQ - 1)) * BB + (gm8 >> 9)) : (size_t)gm8;
#pragma unroll
        for (int ni = 0; ni < 4; ++ni) {
            int col = n0 + warp_n * 32 + ni * 8 + (lane & 3) * 2;
            float2 bv = *(const float2*)(bias1 + col);
            if (BIAS2) {
                float2 b2v = *(const float2*)(bias2 + col);
                bv.x += b2v.x; bv.y += b2v.y;
            }
            float2 v0; v0.x = acc[mi][ni][0] + bv.x; v0.y = acc[mi][ni][1] + bv.y;
            float2 v1; v1.x = acc[mi][ni][2] + bv.x; v1.y = acc[mi][ni][3] + bv.y;
            *(float2*)(C + r0 * (size_t)N + col) = v0;
            *(float2*)(C + r1 * (size_t)N + col) = v1;
        }
    }
}

// ---------------- h0 transpose fill: g_hbuf[0][j*16+b] = h0[b][j] --------------
__global__ void fill_h0_kernel(const float* __restrict__ h0)
{
    int i = blockIdx.x * 256 + threadIdx.x;
    if (i < BB * HH) {
        int b = i >> 10, j = i & (HH - 1);
        g_hbuf[j * BB + b] = h0[i];
    }
}

// ---------------- persistent LSTM scan (R5 body, hierarchical barrier) ---------
__device__ __forceinline__ float sigm(float x) { return 1.f / (1.f + expf(-x)); }

__global__ __launch_bounds__(256)
void lstm_scan(const float* __restrict__ xg, const float* __restrict__ Whh,
               const float* __restrict__ c0, float* __restrict__ outSeq,
               float* __restrict__ state_out, int layer)
{
    extern __shared__ float sm[];
    float* ws  = sm;                          // [1024][32]  128 KB
    float* hs  = sm + HH * 32;                // [1024][16]   64 KB
    float* red = sm + HH * 32 + HH * 16;      // [32][16][8]  16 KB
    const int tid = threadIdx.x, cta = blockIdx.x;
    const int warp = tid >> 5, lane = tid & 31;
    const int rg = lane & 7, bg = lane >> 3;

    // load Whh slice transposed (once; reused for all 512 steps)
    for (int idx = tid; idx < 32 * 256; idx += 256) {
        int r  = idx >> 8;
        int k4 = (idx & 255) * 4;
        int grow = (r >> 3) * HH + cta * 8 + (r & 7);
        float4 w = *(const float4*)(Whh + (size_t)grow * HH + k4);
        ws[(k4 + 0) * 32 + r] = w.x; ws[(k4 + 1) * 32 + r] = w.y;
        ws[(k4 + 2) * 32 + r] = w.z; ws[(k4 + 3) * 32 + r] = w.w;
    }

    const int fb = tid >> 3, fj = tid & 7;
    float c_reg = 0.f;
    if (tid < 128) c_reg = c0[fb * HH + cta * 8 + fj];

    int cur = 0;
    const int k0 = warp * 128;
    for (int t = 0; t < T_SEQ; ++t) {
        // stage h (all 256 threads; .cg = L2)
        const float4* hb = (const float4*)(g_hbuf + cur * (HH * BB));
        float4* hs4 = (float4*)hs;
#pragma unroll
        for (int i = 0; i < 16; ++i) hs4[tid + i * 256] = __ldcg(hb + tid + i * 256);
        __syncthreads();

        u64 acc2[4][2];
#pragma unroll
        for (int i = 0; i < 4; i++) { acc2[i][0] = 0ULL; acc2[i][1] = 0ULL; }

#pragma unroll 4
        for (int k = k0; k < k0 + 128; ++k) {
            ulonglong2 hv = *(const ulonglong2*)&hs[k * 16 + bg * 4];
            float4 wv = *(const float4*)&ws[k * 32 + rg * 4];
            u64 w0 = pack2(wv.x), w1 = pack2(wv.y), w2 = pack2(wv.z), w3 = pack2(wv.w);
            ffma2(acc2[0][0], w0, hv.x); ffma2(acc2[0][1], w0, hv.y);
            ffma2(acc2[1][0], w1, hv.x); ffma2(acc2[1][1], w1, hv.y);
            ffma2(acc2[2][0], w2, hv.x); ffma2(acc2[2][1], w2, hv.y);
            ffma2(acc2[3][0], w3, hv.x); ffma2(acc2[3][1], w3, hv.y);
        }
#pragma unroll
        for (int i = 0; i < 4; i++) {
            float2 p0 = unpack2(acc2[i][0]);
            float2 p1 = unpack2(acc2[i][1]);
            float* rp = &red[(((rg * 4 + i) << 4) + bg * 4) * 8 + warp];
            rp[0 * 8] = p0.x; rp[1 * 8] = p0.y; rp[2 * 8] = p1.x; rp[3 * 8] = p1.y;
        }
        __syncthreads();

        if (tid < 128) {
            int jg = cta * 8 + fj;
            float s[4];
#pragma unroll
            for (int g = 0; g < 4; ++g) {
                const float* rp = &red[(((g * 8 + fj) << 4) + fb) * 8];
                float sum = rp[0] + rp[1] + rp[2] + rp[3] + rp[4] + rp[5] + rp[6] + rp[7];
                s[g] = sum + xg[((size_t)(t * BB + fb)) * G4H + g * HH + jg];
            }
            float ci = sigm(s[0]), cf = sigm(s[1]);
            float cg = tanhf(s[2]), co = sigm(s[3]);
            c_reg = cf * c_reg + ci * cg;
            float hnew = co * tanhf(c_reg);
            outSeq[((size_t)fb * T_SEQ + t) * HH + jg] = hnew;
            g_hbuf[(cur ^ 1) * (HH * BB) + jg * BB + fb] = hnew;
            if (t == T_SEQ - 1 && state_out) {
                state_out[(size_t)layer * BB * HH + fb * HH + jg] = hnew;
                state_out[2 * (size_t)BB * HH + (size_t)layer * BB * HH + fb * HH + jg] = c_reg;
            }
        }

        // ---- hierarchical sense-reversal barrier (2-level atomics) ----
        __syncthreads();
        if (tid == 0) {
            unsigned e = g_epoch;
            __threadfence();
            unsigned* gc = &g_bar1[(cta >> 4) << 5];   // 8 groups, 128B apart
            if (atomicAdd(gc, 1u) == 15u) {
                *gc = 0;
                __threadfence();                       // reset visible before publish chain
                if (atomicAdd(&g_bar2, 1u) == 7u) {
                    g_bar2 = 0;
                    __threadfence();
                    g_epoch = e + 1;
                } else {
                    while (g_epoch == e) { }
                }
            } else {
                while (g_epoch == e) { }
            }
        }
        __syncthreads();
        cur ^= 1;
    }
}

// ---------------- launch -------------------------------------------------------
extern "C" void kernel_launch(void* const* d_in, const int* in_sizes, int n_in,
                              void* d_out, int out_size)
{
    const int*   x    = (const int*)  d_in[0];
    const float* h0   = (const float*)d_in[1];
    const float* c0   = (const float*)d_in[2];
    const float* emb  = (const float*)d_in[3];
    const float* Wih0 = (const float*)d_in[4];
    const float* Whh0 = (const float*)d_in[5];
    const float* bih0 = (const float*)d_in[6];
    const float* bhh0 = (const float*)d_in[7];
    const float* Wih1 = (const float*)d_in[8];
    const float* Whh1 = (const float*)d_in[9];
    const float* bih1 = (const float*)d_in[10];
    const float* bhh1 = (const float*)d_in[11];
    const float* Wfc  = (const float*)d_in[12];
    const float* bfc  = (const float*)d_in[13];
    float* out = (float*)d_out;

    float *xg, *o0, *o1;
    cudaGetSymbolAddress((void**)&xg, g_xg);
    cudaGetSymbolAddress((void**)&o0, g_out0);
    cudaGetSymbolAddress((void**)&o1, g_out1);
    __nv_bfloat16 *a2, *b2, *w2;
    cudaGetSymbolAddress((void**)&a2, g_A2);
    cudaGetSymbolAddress((void**)&b2, g_B2);
    cudaGetSymbolAddress((void**)&w2, g_W2);

    float* state_out = ((size_t)out_size >= LOGN + 4 * BB * HH) ? (out + LOGN) : nullptr;

    const int SMEM_SCAN = (HH * 32 + HH * 16 + 32 * 16 * 8) * 4;   // 212,992 B
    cudaFuncSetAttribute(lstm_scan, cudaFuncAttributeMaxDynamicSharedMemorySize, SMEM_SCAN);
    cudaFuncSetAttribute(hmma_tn<true, true>,   cudaFuncAttributeMaxDynamicSharedMemorySize, HM_SMEM);
    cudaFuncSetAttribute(hmma_tn<false, false>, cudaFuncAttributeMaxDynamicSharedMemorySize, HM_SMEM);

    // Wfc split (hi|lo|hi) — biggest split, up front
    split3<1><<<(VV * HH / 4 + 255) / 256, 256>>>(Wfc, nullptr, b2, VV * HH / 4, HH / 4);

    // ---- layer 0: xg0 = gather(emb,x) @ Wih0^T + bih0 + bhh0 (HMMA, Kexp=1536)
    split3<0><<<(M_ROWS * EE / 4 + 255) / 256, 256>>>(emb, x, a2, M_ROWS * EE / 4, EE / 4);
    split3<1><<<(G4H * EE / 4 + 255) / 256, 256>>>(Wih0, nullptr, w2, G4H * EE / 4, EE / 4);
    hmma_tn<true, true><<<dim3(M_ROWS / 128, G4H / 128), 256, HM_SMEM>>>(
        a2, w2, bih0, bhh0, xg, 3 * EE, G4H);
    fill_h0_kernel<<<(BB * HH + 255) / 256, 256>>>(h0);
    lstm_scan<<<128, 256, SMEM_SCAN>>>(xg, Whh0, c0, o0, state_out, 0);

    // ---- layer 1: xg1 = out0 @ Wih1^T + bih1 + bhh1 (HMMA, Kexp=3072)
    split3<0><<<(M_ROWS * HH / 4 + 255) / 256, 256>>>(o0, nullptr, a2, M_ROWS * HH / 4, HH / 4);
    split3<1><<<(G4H * HH / 4 + 255) / 256, 256>>>(Wih1, nullptr, w2, G4H * HH / 4, HH / 4);
    hmma_tn<true, true><<<dim3(M_ROWS / 128, G4H / 128), 256, HM_SMEM>>>(
        a2, w2, bih1, bhh1, xg, 3 * HH, G4H);
    fill_h0_kernel<<<(BB * HH + 255) / 256, 256>>>(h0 + BB * HH);
    lstm_scan<<<128, 256, SMEM_SCAN>>>(xg, Whh1, c0 + BB * HH, o1, state_out, 1);

    // ---- FC: logits = out1 @ Wfc^T + bfc (HMMA, Kexp=3072)
    split3<0><<<(M_ROWS * HH / 4 + 255) / 256, 256>>>(o1, nullptr, a2, M_ROWS * HH / 4, HH / 4);
    hmma_tn<false, false><<<dim3(M_ROWS / 128, VV / 128), 256, HM_SMEM>>>(
        a2, b2, bfc, nullptr, out, 3 * HH, VV);
}

// round 13
// speedup vs baseline: 1.4939x; 1.0325x over previous
#include <cuda_runtime.h>
#include <cuda_bf16.h>
#include <cstdint>

// ---------------- problem constants ----------------
#define T_SEQ 512
#define BB    16
#define HH    1024
#define EE    512
#define VV    32000
#define G4H   4096
#define M_ROWS (BB * T_SEQ)                     // 8192
#define LOGN  ((size_t)M_ROWS * (size_t)VV)     // 262,144,000

// ---------------- device scratch (static globals: allowed) ----------------
__device__ float g_xg[(size_t)T_SEQ * BB * G4H];      // 134 MB, reused per layer
__device__ float g_out0[(size_t)M_ROWS * HH];         // layer-0 h sequence
__device__ float g_out1[(size_t)M_ROWS * HH];         // layer-1 h sequence
__device__ float g_hbuf[2 * HH * BB];                 // double buffer, [j][b] layout
__device__ unsigned g_bar;                            // zero-init
__device__ volatile unsigned g_epoch;                 // zero-init
__device__ __nv_bfloat16 g_A2[(size_t)M_ROWS * 3072]; // 50 MB  activations (hi|hi|lo)
__device__ __nv_bfloat16 g_B2[(size_t)VV * 3072];     // 197 MB Wfc (hi|lo|hi)
__device__ __nv_bfloat16 g_W2[(size_t)G4H * 3072];    // 25 MB  Wih (hi|lo|hi)

// ---------------- f32x2 packed-FMA helpers ----------------
typedef unsigned long long u64;
__device__ __forceinline__ u64 pack2(float v) {
    u64 r; asm("mov.b64 %0, {%1, %1};" : "=l"(r) : "f"(v)); return r;
}
__device__ __forceinline__ void ffma2(u64& c, u64 a, u64 b) {
    asm("fma.rn.f32x2 %0, %1, %2, %0;" : "+l"(c) : "l"(a), "l"(b));
}
__device__ __forceinline__ float2 unpack2(u64 v) {
    float lo, hi; asm("mov.b64 {%0, %1}, %2;" : "=f"(lo), "=f"(hi) : "l"(v));
    float2 f; f.x = lo; f.y = hi; return f;
}

// ---------------- base-ISA async-copy / ldmatrix / mma helpers ----------------
__device__ __forceinline__ uint32_t smem_u32(const void* p) {
    uint32_t a;
    asm("{ .reg .u64 t; cvta.to.shared.u64 t, %1; cvt.u32.u64 %0, t; }" : "=r"(a) : "l"(p));
    return a;
}
__device__ __forceinline__ void cpa16(uint32_t dst, const void* src) {
    asm volatile("cp.async.cg.shared.global [%0], [%1], 16;" :: "r"(dst), "l"(src));
}
__device__ __forceinline__ void cpa_commit() { asm volatile("cp.async.commit_group;" ::: "memory"); }
template<int N> __device__ __forceinline__ void cpa_wait() {
    asm volatile("cp.async.wait_group %0;" :: "n"(N) : "memory");
}
__device__ __forceinline__ void ldsm4(uint32_t& r0, uint32_t& r1, uint32_t& r2, uint32_t& r3,
                                      uint32_t a) {
    asm volatile("ldmatrix.sync.aligned.m8n8.x4.shared.b16 {%0,%1,%2,%3}, [%4];"
                 : "=r"(r0), "=r"(r1), "=r"(r2), "=r"(r3) : "r"(a));
}
__device__ __forceinline__ void mma_bf16(float* c, const uint32_t* a, const uint32_t* b) {
    asm volatile(
        "mma.sync.aligned.m16n8k16.row.col.f32.bf16.bf16.f32 "
        "{%0,%1,%2,%3}, {%4,%5,%6,%7}, {%8,%9}, {%0,%1,%2,%3};"
        : "+f"(c[0]), "+f"(c[1]), "+f"(c[2]), "+f"(c[3])
        : "r"(a[0]), "r"(a[1]), "r"(a[2]), "r"(a[3]), "r"(b[0]), "r"(b[1]));
}

// ---------------- split-expand: fp32 [rows][K] -> bf16 [rows][3K] ---------------
// MODE 0 (activations): segs (hi, hi, lo).  MODE 1 (weights): segs (hi, lo, hi).
template<int MODE>
__global__ __launch_bounds__(256)
void split3(const float* __restrict__ src, const int* __restrict__ gidx,
            __nv_bfloat16* __restrict__ dst, int n4, int Kdiv4)
{
    int i = blockIdx.x * 256 + threadIdx.x;
    if (i >= n4) return;
    int row = i / Kdiv4;
    int c4  = i - row * Kdiv4;
    int K   = Kdiv4 * 4;
    const float* sp = gidx ? (src + (size_t)gidx[row] * K) : (src + (size_t)row * K);
    float4 v = *(const float4*)(sp + c4 * 4);
    __nv_bfloat16 h0 = __float2bfloat16(v.x), h1 = __float2bfloat16(v.y);
    __nv_bfloat16 h2 = __float2bfloat16(v.z), h3 = __float2bfloat16(v.w);
    __nv_bfloat16 l0 = __float2bfloat16(v.x - __bfloat162float(h0));
    __nv_bfloat16 l1 = __float2bfloat16(v.y - __bfloat162float(h1));
    __nv_bfloat16 l2 = __float2bfloat16(v.z - __bfloat162float(h2));
    __nv_bfloat16 l3 = __float2bfloat16(v.w - __bfloat162float(h3));
    __nv_bfloat162 hA(h0, h1), hB(h2, h3), lA(l0, l1), lB(l2, l3);
    size_t base = (size_t)row * (3 * K) + c4 * 4;
    __nv_bfloat162* d0 = (__nv_bfloat162*)(dst + base);
    __nv_bfloat162* d1 = (__nv_bfloat162*)(dst + base + K);
    __nv_bfloat162* d2 = (__nv_bfloat162*)(dst + base + 2 * K);
    d0[0] = hA; d0[1] = hB;
    if (MODE == 0) { d1[0] = hA; d1[1] = hB; d2[0] = lA; d2[1] = lB; }
    else           { d1[0] = lA; d1[1] = lB; d2[0] = hA; d2[1] = hB; }
}

// ---------------- generic HMMA GEMM (mma.sync bf16) ----------------------------
#define HM_BK      32
#define HM_STAGE_B 16384
#define HM_SMEM    (3 * HM_STAGE_B)     // 49152

__device__ __forceinline__ void hm_fill(uint32_t st, const __nv_bfloat16* a,
                                        const __nv_bfloat16* b, int tid, int Kexp)
{
#pragma unroll
    for (int i = tid; i < 512; i += 256) {
        int r = i >> 2, c = i & 3;
        uint32_t dst = st + r * 64 + ((c ^ ((r >> 1) & 3)) << 4);
        cpa16(dst, a + (size_t)r * Kexp + c * 8);
    }
#pragma unroll
    for (int i = tid; i < 512; i += 256) {
        int r = i >> 2, c = i & 3;
        uint32_t dst = st + 8192 + r * 64 + ((c ^ ((r >> 1) & 3)) << 4);
        cpa16(dst, b + (size_t)r * Kexp + c * 8);
    }
    cpa_commit();
}

template<bool REMAP, bool BIAS2>
__global__ __launch_bounds__(256, 2)
void hmma_tn(const __nv_bfloat16* __restrict__ A2, const __nv_bfloat16* __restrict__ B2,
             const float* __restrict__ bias1, const float* __restrict__ bias2,
             float* __restrict__ C, int Kexp, int N)
{
    extern __shared__ char smem[];
    const uint32_t sbase = smem_u32(smem);
    const int tid = threadIdx.x, wid = tid >> 5, lane = tid & 31;
    const int warp_m = wid & 1, warp_n = wid >> 1;
    const int m0 = blockIdx.x * 128;
    const int n0 = blockIdx.y * 128;

    const __nv_bfloat16* aG = A2 + (size_t)m0 * Kexp;
    const __nv_bfloat16* bG = B2 + (size_t)n0 * Kexp;

    uint32_t aoff[4][2], boff[2][2];
#pragma unroll
    for (int mi = 0; mi < 4; ++mi)
#pragma unroll
        for (int ks = 0; ks < 2; ++ks) {
            int row = warp_m * 64 + mi * 16 + (lane & 15);
            int ch  = ks * 2 + (lane >> 4);
            aoff[mi][ks] = row * 64 + ((ch ^ ((row >> 1) & 3)) << 4);
        }
#pragma unroll
    for (int bi = 0; bi < 2; ++bi)
#pragma unroll
        for (int ks = 0; ks < 2; ++ks) {
            int row = warp_n * 32 + bi * 16 + (lane & 7) + ((lane >> 4) << 3);
            int ch  = ks * 2 + ((lane >> 3) & 1);
            boff[bi][ks] = 8192 + row * 64 + ((ch ^ ((row >> 1) & 3)) << 4);
        }

    float acc[4][4][4];
#pragma unroll
    for (int i = 0; i < 4; i++)
#pragma unroll
        for (int j = 0; j < 4; j++)
#pragma unroll
            for (int e = 0; e < 4; e++) acc[i][j][e] = 0.f;

    const int NKB = Kexp / HM_BK;
    hm_fill(sbase,              aG,         bG,         tid, Kexp);
    hm_fill(sbase + HM_STAGE_B, aG + HM_BK, bG + HM_BK, tid, Kexp);

    for (int kb = 0; kb < NKB; ++kb) {
        const int s = kb % 3;
        cpa_wait<1>();
        __syncthreads();
        if (kb + 2 < NKB)
            hm_fill(sbase + ((kb + 2) % 3) * HM_STAGE_B,
                    aG + (size_t)(kb + 2) * HM_BK, bG + (size_t)(kb + 2) * HM_BK, tid, Kexp);

        const uint32_t sb = sbase + s * HM_STAGE_B;
#pragma unroll
        for (int ks = 0; ks < 2; ++ks) {
            uint32_t a[4][4], b[2][4];
#pragma unroll
            for (int mi = 0; mi < 4; ++mi)
                ldsm4(a[mi][0], a[mi][1], a[mi][2], a[mi][3], sb + aoff[mi][ks]);
#pragma unroll
            for (int bi = 0; bi < 2; ++bi)
                ldsm4(b[bi][0], b[bi][1], b[bi][2], b[bi][3], sb + boff[bi][ks]);
#pragma unroll
            for (int mi = 0; mi < 4; ++mi)
#pragma unroll
                for (int ni = 0; ni < 4; ++ni)
                    mma_bf16(acc[mi][ni], a[mi], &b[ni >> 1][(ni & 1) * 2]);
        }
        __syncthreads();
    }

#pragma unroll
    for (int mi = 0; mi < 4; ++mi) {
        int gm = m0 + warp_m * 64 + mi * 16 + (lane >> 2);
        size_t r0 = REMAP ? (size_t)((gm & (T_SEQ - 1)) * BB + (gm >> 9)) : (size_t)gm;
        int gm8 = gm + 8;
        size_t r1 = REMAP ? (size_t)((gm8 & (T_SEQ - 1)) * BB + (gm8 >> 9)) : (size_t)gm8;
#pragma unroll
        for (int ni = 0; ni < 4; ++ni) {
            int col = n0 + warp_n * 32 + ni * 8 + (lane & 3) * 2;
            float2 bv = *(const float2*)(bias1 + col);
            if (BIAS2) {
                float2 b2v = *(const float2*)(bias2 + col);
                bv.x += b2v.x; bv.y += b2v.y;
            }
            float2 v0; v0.x = acc[mi][ni][0] + bv.x; v0.y = acc[mi][ni][1] + bv.y;
            float2 v1; v1.x = acc[mi][ni][2] + bv.x; v1.y = acc[mi][ni][3] + bv.y;
            *(float2*)(C + r0 * (size_t)N + col) = v0;
            *(float2*)(C + r1 * (size_t)N + col) = v1;
        }
    }
}

// ---------------- h0 transpose fill: g_hbuf[0][j*16+b] = h0[b][j] --------------
__global__ void fill_h0_kernel(const float* __restrict__ h0)
{
    int i = blockIdx.x * 256 + threadIdx.x;
    if (i < BB * HH) {
        int b = i >> 10, j = i & (HH - 1);
        g_hbuf[j * BB + b] = h0[i];
    }
}

// ---------------- persistent LSTM scan (R5 + critical-path code motion) --------
__device__ __forceinline__ float sigm(float x) { return 1.f / (1.f + expf(-x)); }

__global__ __launch_bounds__(256)
void lstm_scan(const float* __restrict__ xg, const float* __restrict__ Whh,
               const float* __restrict__ c0, float* __restrict__ outSeq,
               float* __restrict__ state_out, int layer)
{
    extern __shared__ float sm[];
    float* ws  = sm;                          // [1024][32]  128 KB
    float* hs  = sm + HH * 32;                // [1024][16]   64 KB
    float* red = sm + HH * 32 + HH * 16;      // [32][16][8]  16 KB
    const int tid = threadIdx.x, cta = blockIdx.x;
    const int warp = tid >> 5, lane = tid & 31;
    const int rg = lane & 7, bg = lane >> 3;

    // load Whh slice transposed (once; reused for all 512 steps)
    for (int idx = tid; idx < 32 * 256; idx += 256) {
        int r  = idx >> 8;
        int k4 = (idx & 255) * 4;
        int grow = (r >> 3) * HH + cta * 8 + (r & 7);
        float4 w = *(const float4*)(Whh + (size_t)grow * HH + k4);
        ws[(k4 + 0) * 32 + r] = w.x; ws[(k4 + 1) * 32 + r] = w.y;
        ws[(k4 + 2) * 32 + r] = w.z; ws[(k4 + 3) * 32 + r] = w.w;
    }

    const int fb = tid >> 3, fj = tid & 7;
    float c_reg = 0.f;
    if (tid < 128) c_reg = c0[fb * HH + cta * 8 + fj];

    int cur = 0;
    const int k0 = warp * 128;
    for (int t = 0; t < T_SEQ; ++t) {
        // prefetch xg into registers (independent of h; hides under k-loop)
        float xpre0 = 0.f, xpre1 = 0.f, xpre2 = 0.f, xpre3 = 0.f;
        if (tid < 128) {
            const float* xp = xg + (size_t)(t * BB + fb) * G4H + cta * 8 + fj;
            xpre0 = __ldcg(xp);
            xpre1 = __ldcg(xp + HH);
            xpre2 = __ldcg(xp + 2 * HH);
            xpre3 = __ldcg(xp + 3 * HH);
        }

        // stage h (all 256 threads; .cg = L2)
        const float4* hb = (const float4*)(g_hbuf + cur * (HH * BB));
        float4* hs4 = (float4*)hs;
#pragma unroll
        for (int i = 0; i < 16; ++i) hs4[tid + i * 256] = __ldcg(hb + tid + i * 256);
        __syncthreads();

        u64 acc2[4][2];
#pragma unroll
        for (int i = 0; i < 4; i++) { acc2[i][0] = 0ULL; acc2[i][1] = 0ULL; }

#pragma unroll 4
        for (int k = k0; k < k0 + 128; ++k) {
            ulonglong2 hv = *(const ulonglong2*)&hs[k * 16 + bg * 4];
            float4 wv = *(const float4*)&ws[k * 32 + rg * 4];
            u64 w0 = pack2(wv.x), w1 = pack2(wv.y), w2 = pack2(wv.z), w3 = pack2(wv.w);
            ffma2(acc2[0][0], w0, hv.x); ffma2(acc2[0][1], w0, hv.y);
            ffma2(acc2[1][0], w1, hv.x); ffma2(acc2[1][1], w1, hv.y);
            ffma2(acc2[2][0], w2, hv.x); ffma2(acc2[2][1], w2, hv.y);
            ffma2(acc2[3][0], w3, hv.x); ffma2(acc2[3][1], w3, hv.y);
        }
#pragma unroll
        for (int i = 0; i < 4; i++) {
            float2 p0 = unpack2(acc2[i][0]);
            float2 p1 = unpack2(acc2[i][1]);
            float* rp = &red[(((rg * 4 + i) << 4) + bg * 4) * 8 + warp];
            rp[0 * 8] = p0.x; rp[1 * 8] = p0.y; rp[2 * 8] = p1.x; rp[3 * 8] = p1.y;
        }
        __syncthreads();

        float hnew = 0.f;
        if (tid < 128) {
            int jg = cta * 8 + fj;
            float s[4];
#pragma unroll
            for (int g = 0; g < 4; ++g) {
                const float* rp = &red[(((g * 8 + fj) << 4) + fb) * 8];
                s[g] = rp[0] + rp[1] + rp[2] + rp[3] + rp[4] + rp[5] + rp[6] + rp[7];
            }
            s[0] += xpre0; s[1] += xpre1; s[2] += xpre2; s[3] += xpre3;
            float ci = sigm(s[0]), cf = sigm(s[1]);
            float cg = tanhf(s[2]), co = sigm(s[3]);
            c_reg = cf * c_reg + ci * cg;
            hnew = co * tanhf(c_reg);
            g_hbuf[(cur ^ 1) * (HH * BB) + jg * BB + fb] = hnew;     // consumers need this
            if (t == T_SEQ - 1 && state_out) {
                state_out[(size_t)layer * BB * HH + fb * HH + jg] = hnew;
                state_out[2 * (size_t)BB * HH + (size_t)layer * BB * HH + fb * HH + jg] = c_reg;
            }
        }
        __threadfence();          // publish h (fence precedes outSeq => doesn't wait on it)
        if (tid < 128) {
            int jg = cta * 8 + fj;
            outSeq[((size_t)fb * T_SEQ + t) * HH + jg] = hnew;       // lazy DRAM store
        }

        // ---- R5 grid barrier (sense-reversal; validated twice) ----
        __syncthreads();
        if (tid == 0) {
            unsigned e = g_epoch;
            __threadfence();
            if (atomicAdd(&g_bar, 1u) == (unsigned)gridDim.x - 1u) {
                g_bar = 0;
                __threadfence();
                g_epoch = e + 1;
            } else {
                while (g_epoch == e) { }
            }
        }
        __syncthreads();
        cur ^= 1;
    }
}

// ---------------- launch -------------------------------------------------------
extern "C" void kernel_launch(void* const* d_in, const int* in_sizes, int n_in,
                              void* d_out, int out_size)
{
    const int*   x    = (const int*)  d_in[0];
    const float* h0   = (const float*)d_in[1];
    const float* c0   = (const float*)d_in[2];
    const float* emb  = (const float*)d_in[3];
    const float* Wih0 = (const float*)d_in[4];
    const float* Whh0 = (const float*)d_in[5];
    const float* bih0 = (const float*)d_in[6];
    const float* bhh0 = (const float*)d_in[7];
    const float* Wih1 = (const float*)d_in[8];
    const float* Whh1 = (const float*)d_in[9];
    const float* bih1 = (const float*)d_in[10];
    const float* bhh1 = (const float*)d_in[11];
    const float* Wfc  = (const float*)d_in[12];
    const float* bfc  = (const float*)d_in[13];
    float* out = (float*)d_out;

    float *xg, *o0, *o1;
    cudaGetSymbolAddress((void**)&xg, g_xg);
    cudaGetSymbolAddress((void**)&o0, g_out0);
    cudaGetSymbolAddress((void**)&o1, g_out1);
    __nv_bfloat16 *a2, *b2, *w2;
    cudaGetSymbolAddress((void**)&a2, g_A2);
    cudaGetSymbolAddress((void**)&b2, g_B2);
    cudaGetSymbolAddress((void**)&w2, g_W2);

    float* state_out = ((size_t)out_size >= LOGN + 4 * BB * HH) ? (out + LOGN) : nullptr;

    const int SMEM_SCAN = (HH * 32 + HH * 16 + 32 * 16 * 8) * 4;   // 212,992 B
    cudaFuncSetAttribute(lstm_scan, cudaFuncAttributeMaxDynamicSharedMemorySize, SMEM_SCAN);
    cudaFuncSetAttribute(hmma_tn<true, true>,   cudaFuncAttributeMaxDynamicSharedMemorySize, HM_SMEM);
    cudaFuncSetAttribute(hmma_tn<false, false>, cudaFuncAttributeMaxDynamicSharedMemorySize, HM_SMEM);

    // Wfc split (hi|lo|hi) — biggest split, up front
    split3<1><<<(VV * HH / 4 + 255) / 256, 256>>>(Wfc, nullptr, b2, VV * HH / 4, HH / 4);

    // ---- layer 0: xg0 = gather(emb,x) @ Wih0^T + bih0 + bhh0 (HMMA, Kexp=1536)
    split3<0><<<(M_ROWS * EE / 4 + 255) / 256, 256>>>(emb, x, a2, M_ROWS * EE / 4, EE / 4);
    split3<1><<<(G4H * EE / 4 + 255) / 256, 256>>>(Wih0, nullptr, w2, G4H * EE / 4, EE / 4);
    hmma_tn<true, true><<<dim3(M_ROWS / 128, G4H / 128), 256, HM_SMEM>>>(
        a2, w2, bih0, bhh0, xg, 3 * EE, G4H);
    fill_h0_kernel<<<(BB * HH + 255) / 256, 256>>>(h0);
    lstm_scan<<<128, 256, SMEM_SCAN>>>(xg, Whh0, c0, o0, state_out, 0);

    // ---- layer 1: xg1 = out0 @ Wih1^T + bih1 + bhh1 (HMMA, Kexp=3072)
    split3<0><<<(M_ROWS * HH / 4 + 255) / 256, 256>>>(o0, nullptr, a2, M_ROWS * HH / 4, HH / 4);
    split3<1><<<(G4H * HH / 4 + 255) / 256, 256>>>(Wih1, nullptr, w2, G4H * HH / 4, HH / 4);
    hmma_tn<true, true><<<dim3(M_ROWS / 128, G4H / 128), 256, HM_SMEM>>>(
        a2, w2, bih1, bhh1, xg, 3 * HH, G4H);
    fill_h0_kernel<<<(BB * HH + 255) / 256, 256>>>(h0 + BB * HH);
    lstm_scan<<<128, 256, SMEM_SCAN>>>(xg, Whh1, c0 + BB * HH, o1, state_out, 1);

    // ---- FC: logits = out1 @ Wfc^T + bfc (HMMA, Kexp=3072)
    split3<0><<<(M_ROWS * HH / 4 + 255) / 256, 256>>>(o1, nullptr, a2, M_ROWS * HH / 4, HH / 4);
    hmma_tn<false, false><<<dim3(M_ROWS / 128, VV / 128), 256, HM_SMEM>>>(
        a2, b2, bfc, nullptr, out, 3 * HH, VV);
}

// round 15
// speedup vs baseline: 2.2261x; 1.4901x over previous
#include <cuda_runtime.h>
#include <cuda_bf16.h>
#include <cstdint>

// ---------------- problem constants ----------------
#define T_SEQ 512
#define BB    16
#define HH    1024
#define EE    512
#define VV    32000
#define G4H   4096
#define M_ROWS (BB * T_SEQ)                     // 8192
#define LOGN  ((size_t)M_ROWS * (size_t)VV)     // 262,144,000

// ---------------- device scratch (static globals: allowed) ----------------
__device__ float g_xg[(size_t)T_SEQ * BB * G4H];      // 134 MB, reused per layer
__device__ float g_out0[(size_t)M_ROWS * HH];         // layer-0 h sequence
__device__ float g_out1[(size_t)M_ROWS * HH];         // layer-1 h sequence
__device__ __nv_bfloat16 g_hH[2 * BB * HH];           // h hi, [cur][b][j]
__device__ __nv_bfloat16 g_hL[2 * BB * HH];           // h lo, [cur][b][j]
__device__ unsigned g_bar;                            // zero-init
__device__ volatile unsigned g_epoch;                 // zero-init
__device__ __nv_bfloat16 g_A2[(size_t)M_ROWS * 3072]; // 50 MB  activations (hi|hi|lo)
__device__ __nv_bfloat16 g_B2[(size_t)VV * 3072];     // 197 MB Wfc (hi|lo|hi)
__device__ __nv_bfloat16 g_W2[(size_t)G4H * 3072];    // 25 MB  Wih (hi|lo|hi)

// ---------------- base-ISA async-copy / ldmatrix / mma helpers ----------------
__device__ __forceinline__ uint32_t smem_u32(const void* p) {
    uint32_t a;
    asm("{ .reg .u64 t; cvta.to.shared.u64 t, %1; cvt.u32.u64 %0, t; }" : "=r"(a) : "l"(p));
    return a;
}
__device__ __forceinline__ void cpa16(uint32_t dst, const void* src) {
    asm volatile("cp.async.cg.shared.global [%0], [%1], 16;" :: "r"(dst), "l"(src));
}
__device__ __forceinline__ void cpa_commit() { asm volatile("cp.async.commit_group;" ::: "memory"); }
template<int N> __device__ __forceinline__ void cpa_wait() {
    asm volatile("cp.async.wait_group %0;" :: "n"(N) : "memory");
}
__device__ __forceinline__ void ldsm4(uint32_t& r0, uint32_t& r1, uint32_t& r2, uint32_t& r3,
                                      uint32_t a) {
    asm volatile("ldmatrix.sync.aligned.m8n8.x4.shared.b16 {%0,%1,%2,%3}, [%4];"
                 : "=r"(r0), "=r"(r1), "=r"(r2), "=r"(r3) : "r"(a));
}
__device__ __forceinline__ void mma_bf16(float* c, const uint32_t* a, const uint32_t* b) {
    asm volatile(
        "mma.sync.aligned.m16n8k16.row.col.f32.bf16.bf16.f32 "
        "{%0,%1,%2,%3}, {%4,%5,%6,%7}, {%8,%9}, {%0,%1,%2,%3};"
        : "+f"(c[0]), "+f"(c[1]), "+f"(c[2]), "+f"(c[3])
        : "r"(a[0]), "r"(a[1]), "r"(a[2]), "r"(a[3]), "r"(b[0]), "r"(b[1]));
}

// ---------------- split-expand: fp32 [rows][K] -> bf16 [rows][3K] ---------------
// MODE 0 (activations): segs (hi, hi, lo).  MODE 1 (weights): segs (hi, lo, hi).
template<int MODE>
__global__ __launch_bounds__(256)
void split3(const float* __restrict__ src, const int* __restrict__ gidx,
            __nv_bfloat16* __restrict__ dst, int n4, int Kdiv4)
{
    int i = blockIdx.x * 256 + threadIdx.x;
    if (i >= n4) return;
    int row = i / Kdiv4;
    int c4  = i - row * Kdiv4;
    int K   = Kdiv4 * 4;
    const float* sp = gidx ? (src + (size_t)gidx[row] * K) : (src + (size_t)row * K);
    float4 v = *(const float4*)(sp + c4 * 4);
    __nv_bfloat16 h0 = __float2bfloat16(v.x), h1 = __float2bfloat16(v.y);
    __nv_bfloat16 h2 = __float2bfloat16(v.z), h3 = __float2bfloat16(v.w);
    __nv_bfloat16 l0 = __float2bfloat16(v.x - __bfloat162float(h0));
    __nv_bfloat16 l1 = __float2bfloat16(v.y - __bfloat162float(h1));
    __nv_bfloat16 l2 = __float2bfloat16(v.z - __bfloat162float(h2));
    __nv_bfloat16 l3 = __float2bfloat16(v.w - __bfloat162float(h3));
    __nv_bfloat162 hA(h0, h1), hB(h2, h3), lA(l0, l1), lB(l2, l3);
    size_t base = (size_t)row * (3 * K) + c4 * 4;
    __nv_bfloat162* d0 = (__nv_bfloat162*)(dst + base);
    __nv_bfloat162* d1 = (__nv_bfloat162*)(dst + base + K);
    __nv_bfloat162* d2 = (__nv_bfloat162*)(dst + base + 2 * K);
    d0[0] = hA; d0[1] = hB;
    if (MODE == 0) { d1[0] = hA; d1[1] = hB; d2[0] = lA; d2[1] = lB; }
    else           { d1[0] = lA; d1[1] = lB; d2[0] = hA; d2[1] = hB; }
}

// ---------------- generic HMMA GEMM (mma.sync bf16) ----------------------------
#define HM_BK      32
#define HM_STAGE_B 16384
#define HM_SMEM    (3 * HM_STAGE_B)     // 49152

__device__ __forceinline__ void hm_fill(uint32_t st, const __nv_bfloat16* a,
                                        const __nv_bfloat16* b, int tid, int Kexp)
{
#pragma unroll
    for (int i = tid; i < 512; i += 256) {
        int r = i >> 2, c = i & 3;
        uint32_t dst = st + r * 64 + ((c ^ ((r >> 1) & 3)) << 4);
        cpa16(dst, a + (size_t)r * Kexp + c * 8);
    }
#pragma unroll
    for (int i = tid; i < 512; i += 256) {
        int r = i >> 2, c = i & 3;
        uint32_t dst = st + 8192 + r * 64 + ((c ^ ((r >> 1) & 3)) << 4);
        cpa16(dst, b + (size_t)r * Kexp + c * 8);
    }
    cpa_commit();
}

template<bool REMAP, bool BIAS2>
__global__ __launch_bounds__(256, 2)
void hmma_tn(const __nv_bfloat16* __restrict__ A2, const __nv_bfloat16* __restrict__ B2,
             const float* __restrict__ bias1, const float* __restrict__ bias2,
             float* __restrict__ C, int Kexp, int N)
{
    extern __shared__ char smem[];
    const uint32_t sbase = smem_u32(smem);
    const int tid = threadIdx.x, wid = tid >> 5, lane = tid & 31;
    const int warp_m = wid & 1, warp_n = wid >> 1;
    const int m0 = blockIdx.x * 128;
    const int n0 = blockIdx.y * 128;

    const __nv_bfloat16* aG = A2 + (size_t)m0 * Kexp;
    const __nv_bfloat16* bG = B2 + (size_t)n0 * Kexp;

    uint32_t aoff[4][2], boff[2][2];
#pragma unroll
    for (int mi = 0; mi < 4; ++mi)
#pragma unroll
        for (int ks = 0; ks < 2; ++ks) {
            int row = warp_m * 64 + mi * 16 + (lane & 15);
            int ch  = ks * 2 + (lane >> 4);
            aoff[mi][ks] = row * 64 + ((ch ^ ((row >> 1) & 3)) << 4);
        }
#pragma unroll
    for (int bi = 0; bi < 2; ++bi)
#pragma unroll
        for (int ks = 0; ks < 2; ++ks) {
            int row = warp_n * 32 + bi * 16 + (lane & 7) + ((lane >> 4) << 3);
            int ch  = ks * 2 + ((lane >> 3) & 1);
            boff[bi][ks] = 8192 + row * 64 + ((ch ^ ((row >> 1) & 3)) << 4);
        }

    float acc[4][4][4];
#pragma unroll
    for (int i = 0; i < 4; i++)
#pragma unroll
        for (int j = 0; j < 4; j++)
#pragma unroll
            for (int e = 0; e < 4; e++) acc[i][j][e] = 0.f;

    const int NKB = Kexp / HM_BK;
    hm_fill(sbase,              aG,         bG,         tid, Kexp);
    hm_fill(sbase + HM_STAGE_B, aG + HM_BK, bG + HM_BK, tid, Kexp);

    for (int kb = 0; kb < NKB; ++kb) {
        const int s = kb % 3;
        cpa_wait<1>();
        __syncthreads();
        if (kb + 2 < NKB)
            hm_fill(sbase + ((kb + 2) % 3) * HM_STAGE_B,
                    aG + (size_t)(kb + 2) * HM_BK, bG + (size_t)(kb + 2) * HM_BK, tid, Kexp);

        const uint32_t sb = sbase + s * HM_STAGE_B;
#pragma unroll
        for (int ks = 0; ks < 2; ++ks) {
            uint32_t a[4][4], b[2][4];
#pragma unroll
            for (int mi = 0; mi < 4; ++mi)
                ldsm4(a[mi][0], a[mi][1], a[mi][2], a[mi][3], sb + aoff[mi][ks]);
#pragma unroll
            for (int bi = 0; bi < 2; ++bi)
                ldsm4(b[bi][0], b[bi][1], b[bi][2], b[bi][3], sb + boff[bi][ks]);
#pragma unroll
            for (int mi = 0; mi < 4; ++mi)
#pragma unroll
                for (int ni = 0; ni < 4; ++ni)
                    mma_bf16(acc[mi][ni], a[mi], &b[ni >> 1][(ni & 1) * 2]);
        }
        __syncthreads();
    }

#pragma unroll
    for (int mi = 0; mi < 4; ++mi) {
        int gm = m0 + warp_m * 64 + mi * 16 + (lane >> 2);
        size_t r0 = REMAP ? (size_t)((gm & (T_SEQ - 1)) * BB + (gm >> 9)) : (size_t)gm;
        int gm8 = gm + 8;
        size_t r1 = REMAP ? (size_t)((gm8 & (T_SEQ - 1)) * BB + (gm8 >> 9)) : (size_t)gm8;
#pragma unroll
        for (int ni = 0; ni < 4; ++ni) {
            int col = n0 + warp_n * 32 + ni * 8 + (lane & 3) * 2;
            float2 bv = *(const float2*)(bias1 + col);
            if (BIAS2) {
                float2 b2v = *(const float2*)(bias2 + col);
                bv.x += b2v.x; bv.y += b2v.y;
            }
            float2 v0; v0.x = acc[mi][ni][0] + bv.x; v0.y = acc[mi][ni][1] + bv.y;
            float2 v1; v1.x = acc[mi][ni][2] + bv.x; v1.y = acc[mi][ni][3] + bv.y;
            *(float2*)(C + r0 * (size_t)N + col) = v0;
            *(float2*)(C + r1 * (size_t)N + col) = v1;
        }
    }
}

// ---------------- h0 fill: bf16 hi/lo, [b][j], buffer 0 ------------------------
__global__ void fill_h0_kernel(const float* __restrict__ h0)
{
    int i = blockIdx.x * 256 + threadIdx.x;
    if (i < BB * HH) {
        float v = h0[i];
        __nv_bfloat16 hi = __float2bfloat16(v);
        __nv_bfloat16 lo = __float2bfloat16(v - __bfloat162float(hi));
        g_hH[i] = hi;
        g_hL[i] = lo;
    }
}

// ---------------- persistent LSTM scan (R5 skeleton, HMMA matvec) --------------
// smem: wsH [32r][1024k] bf16 swizzled 64KB @0 | wsL 64KB @65536
//       HsH per-warp [16n][136k] bf16 @131072 | HsL @165888 | red [8w][32r][16b] @200704
#define WS_BYTES  65536
#define HS_ROW    272
#define HS_WARP   (16 * HS_ROW)               // 4352
#define HSH_OFF   131072
#define HSL_OFF   (HSH_OFF + 8 * HS_WARP)     // 165888
#define RED_OFF   (HSL_OFF + 8 * HS_WARP)     // 200704
#define SCAN_SMEM (RED_OFF + 8 * 32 * 16 * 4) // 217088

__device__ __forceinline__ float sigm(float x) { return 1.f / (1.f + expf(-x)); }

__global__ __launch_bounds__(256)
void lstm_scan(const float* __restrict__ xg, const float* __restrict__ Whh,
               const float* __restrict__ c0, float* __restrict__ outSeq,
               float* __restrict__ state_out, int layer)
{
    extern __shared__ char smc[];
    const uint32_t sb = smem_u32(smc);
    float* red = (float*)(smc + RED_OFF);
    const int tid = threadIdx.x, cta = blockIdx.x;
    const int warp = tid >> 5, lane = tid & 31;

    // ---- init: convert Whh slice -> bf16 hi/lo, swizzled A layout (once) ----
    for (int idx = tid; idx < 32 * 128; idx += 256) {
        int r  = idx >> 7, ch = idx & 127;
        int grow = (r >> 3) * HH + cta * 8 + (r & 7);       // r = g*8 + jl
        const float* wp = Whh + (size_t)grow * HH + ch * 8;
        float4 f0 = *(const float4*)wp;
        float4 f1 = *(const float4*)(wp + 4);
        float v[8] = {f0.x, f0.y, f0.z, f0.w, f1.x, f1.y, f1.z, f1.w};
        uint32_t off = (uint32_t)(r * 2048 + ((ch ^ (r & 7)) << 4));
        __nv_bfloat162* dh = (__nv_bfloat162*)(smc + off);
        __nv_bfloat162* dl = (__nv_bfloat162*)(smc + WS_BYTES + off);
#pragma unroll
        for (int p = 0; p < 4; ++p) {
            __nv_bfloat16 h0b = __float2bfloat16(v[p * 2]);
            __nv_bfloat16 h1b = __float2bfloat16(v[p * 2 + 1]);
            __nv_bfloat16 l0b = __float2bfloat16(v[p * 2]     - __bfloat162float(h0b));
            __nv_bfloat16 l1b = __float2bfloat16(v[p * 2 + 1] - __bfloat162float(h1b));
            dh[p] = __nv_bfloat162(h0b, h1b);
            dl[p] = __nv_bfloat162(l0b, l1b);
        }
    }

    const int fb = tid >> 3, fj = tid & 7;
    float c_reg = 0.f;
    if (tid < 128) c_reg = c0[fb * HH + cta * 8 + fj];
    __syncthreads();                                   // ws ready

    // precomputed ldmatrix lane offsets (A chunks: THIS WARP'S k-slice!)
    uint32_t aoff[2][8];
#pragma unroll
    for (int mi = 0; mi < 2; ++mi)
#pragma unroll
        for (int ks = 0; ks < 8; ++ks) {
            int row = mi * 16 + (lane & 15);
            int ch  = warp * 16 + ks * 2 + (lane >> 4);   // FIX: + warp*16
            aoff[mi][ks] = (uint32_t)(row * 2048 + ((ch ^ (row & 7)) << 4));
        }
    uint32_t boff[8];
#pragma unroll
    for (int ks = 0; ks < 8; ++ks) {
        int nrow = (lane & 7) + ((lane >> 4) << 3);
        int ch   = ks * 2 + ((lane >> 3) & 1);
        boff[ks] = (uint32_t)(HSH_OFF + warp * HS_WARP + nrow * HS_ROW + ch * 16);
    }

    int cur = 0;
    const int k0 = warp * 128;
    for (int t = 0; t < T_SEQ; ++t) {
        // stage own k-slice of h (bf16 hi/lo) into per-warp Hs
        {
            const __nv_bfloat16* hHsrc = g_hH + (size_t)cur * (BB * HH) + k0;
            const __nv_bfloat16* hLsrc = g_hL + (size_t)cur * (BB * HH) + k0;
            char* dH = smc + HSH_OFF + warp * HS_WARP + lane * 8;
            char* dL = smc + HSL_OFF + warp * HS_WARP + lane * 8;
#pragma unroll
            for (int b = 0; b < 16; ++b) {
                uint2 vh = __ldcg((const uint2*)(hHsrc + b * HH) + lane);
                uint2 vl = __ldcg((const uint2*)(hLsrc + b * HH) + lane);
                *(uint2*)(dH + b * HS_ROW) = vh;
                *(uint2*)(dL + b * HS_ROW) = vl;
            }
        }
        __syncwarp();

        float D[2][2][4];
#pragma unroll
        for (int mi = 0; mi < 2; ++mi)
#pragma unroll
            for (int ni = 0; ni < 2; ++ni)
#pragma unroll
                for (int e = 0; e < 4; ++e) D[mi][ni][e] = 0.f;

#pragma unroll
        for (int ks = 0; ks < 8; ++ks) {
            uint32_t ah[2][4], al[2][4], bh[4], bl[4];
#pragma unroll
            for (int mi = 0; mi < 2; ++mi) {
                ldsm4(ah[mi][0], ah[mi][1], ah[mi][2], ah[mi][3], sb + aoff[mi][ks]);
                ldsm4(al[mi][0], al[mi][1], al[mi][2], al[mi][3], sb + WS_BYTES + aoff[mi][ks]);
            }
            ldsm4(bh[0], bh[1], bh[2], bh[3], sb + boff[ks]);
            ldsm4(bl[0], bl[1], bl[2], bl[3], sb + boff[ks] + (HSL_OFF - HSH_OFF));
#pragma unroll
            for (int mi = 0; mi < 2; ++mi)
#pragma unroll
                for (int ni = 0; ni < 2; ++ni) {
                    mma_bf16(D[mi][ni], ah[mi], &bh[ni * 2]);
                    mma_bf16(D[mi][ni], al[mi], &bh[ni * 2]);
                    mma_bf16(D[mi][ni], ah[mi], &bl[ni * 2]);
                    mma_bf16(D[mi][ni], al[mi], &bl[ni * 2]);
                }
        }

        // write partials: red[warp][r][b]
        {
            float* rp = red + warp * 512;
#pragma unroll
            for (int mi = 0; mi < 2; ++mi)
#pragma unroll
                for (int ni = 0; ni < 2; ++ni) {
                    int r0 = mi * 16 + (lane >> 2);
                    int cb = ni * 8 + (lane & 3) * 2;
                    *(float2*)(rp + r0 * 16 + cb)       = make_float2(D[mi][ni][0], D[mi][ni][1]);
                    *(float2*)(rp + (r0 + 8) * 16 + cb) = make_float2(D[mi][ni][2], D[mi][ni][3]);
                }
        }
        __syncthreads();

        if (tid < 128) {
            int jg = cta * 8 + fj;
            float s[4];
#pragma unroll
            for (int g = 0; g < 4; ++g) {
                int base = (g * 8 + fj) * 16 + fb;
                float sum = 0.f;
#pragma unroll
                for (int w = 0; w < 8; ++w) sum += red[w * 512 + base];
                s[g] = sum + xg[((size_t)(t * BB + fb)) * G4H + g * HH + jg];
            }
            float ci = sigm(s[0]), cf = sigm(s[1]);
            float cg = tanhf(s[2]), co = sigm(s[3]);
            c_reg = cf * c_reg + ci * cg;
            float hnew = co * tanhf(c_reg);
            outSeq[((size_t)fb * T_SEQ + t) * HH + jg] = hnew;
            __nv_bfloat16 hhi = __float2bfloat16(hnew);
            __nv_bfloat16 hlo = __float2bfloat16(hnew - __bfloat162float(hhi));
            size_t hoff = (size_t)(cur ^ 1) * (BB * HH) + fb * HH + jg;
            g_hH[hoff] = hhi;
            g_hL[hoff] = hlo;
            if (t == T_SEQ - 1 && state_out) {
                state_out[(size_t)layer * BB * HH + fb * HH + jg] = hnew;
                state_out[2 * (size_t)BB * HH + (size_t)layer * BB * HH + fb * HH + jg] = c_reg;
            }
        }

        // ---- R5 grid barrier (sense-reversal; validated) ----
        __syncthreads();
        if (tid == 0) {
            unsigned e = g_epoch;
            __threadfence();
            if (atomicAdd(&g_bar, 1u) == (unsigned)gridDim.x - 1u) {
                g_bar = 0;
                __threadfence();
                g_epoch = e + 1;
            } else {
                while (g_epoch == e) { }
            }
        }
        __syncthreads();
        cur ^= 1;
    }
}

// ---------------- launch -------------------------------------------------------
extern "C" void kernel_launch(void* const* d_in, const int* in_sizes, int n_in,
                              void* d_out, int out_size)
{
    const int*   x    = (const int*)  d_in[0];
    const float* h0   = (const float*)d_in[1];
    const float* c0   = (const float*)d_in[2];
    const float* emb  = (const float*)d_in[3];
    const float* Wih0 = (const float*)d_in[4];
    const float* Whh0 = (const float*)d_in[5];
    const float* bih0 = (const float*)d_in[6];
    const float* bhh0 = (const float*)d_in[7];
    const float* Wih1 = (const float*)d_in[8];
    const float* Whh1 = (const float*)d_in[9];
    const float* bih1 = (const float*)d_in[10];
    const float* bhh1 = (const float*)d_in[11];
    const float* Wfc  = (const float*)d_in[12];
    const float* bfc  = (const float*)d_in[13];
    float* out = (float*)d_out;

    float *xg, *o0, *o1;
    cudaGetSymbolAddress((void**)&xg, g_xg);
    cudaGetSymbolAddress((void**)&o0, g_out0);
    cudaGetSymbolAddress((void**)&o1, g_out1);
    __nv_bfloat16 *a2, *b2, *w2;
    cudaGetSymbolAddress((void**)&a2, g_A2);
    cudaGetSymbolAddress((void**)&b2, g_B2);
    cudaGetSymbolAddress((void**)&w2, g_W2);

    float* state_out = ((size_t)out_size >= LOGN + 4 * BB * HH) ? (out + LOGN) : nullptr;

    cudaFuncSetAttribute(lstm_scan, cudaFuncAttributeMaxDynamicSharedMemorySize, SCAN_SMEM);
    cudaFuncSetAttribute(hmma_tn<true, true>,   cudaFuncAttributeMaxDynamicSharedMemorySize, HM_SMEM);
    cudaFuncSetAttribute(hmma_tn<false, false>, cudaFuncAttributeMaxDynamicSharedMemorySize, HM_SMEM);

    // Wfc split (hi|lo|hi) — biggest split, up front
    split3<1><<<(VV * HH / 4 + 255) / 256, 256>>>(Wfc, nullptr, b2, VV * HH / 4, HH / 4);

    // ---- layer 0: xg0 = gather(emb,x) @ Wih0^T + bih0 + bhh0 (HMMA, Kexp=1536)
    split3<0><<<(M_ROWS * EE / 4 + 255) / 256, 256>>>(emb, x, a2, M_ROWS * EE / 4, EE / 4);
    split3<1><<<(G4H * EE / 4 + 255) / 256, 256>>>(Wih0, nullptr, w2, G4H * EE / 4, EE / 4);
    hmma_tn<true, true><<<dim3(M_ROWS / 128, G4H / 128), 256, HM_SMEM>>>(
        a2, w2, bih0, bhh0, xg, 3 * EE, G4H);
    fill_h0_kernel<<<(BB * HH + 255) / 256, 256>>>(h0);
    lstm_scan<<<128, 256, SCAN_SMEM>>>(xg, Whh0, c0, o0, state_out, 0);

    // ---- layer 1: xg1 = out0 @ Wih1^T + bih1 + bhh1 (HMMA, Kexp=3072)
    split3<0><<<(M_ROWS * HH / 4 + 255) / 256, 256>>>(o0, nullptr, a2, M_ROWS * HH / 4, HH / 4);
    split3<1><<<(G4H * HH / 4 + 255) / 256, 256>>>(Wih1, nullptr, w2, G4H * HH / 4, HH / 4);
    hmma_tn<true, true><<<dim3(M_ROWS / 128, G4H / 128), 256, HM_SMEM>>>(
        a2, w2, bih1, bhh1, xg, 3 * HH, G4H);
    fill_h0_kernel<<<(BB * HH + 255) / 256, 256>>>(h0 + BB * HH);
    lstm_scan<<<128, 256, SCAN_SMEM>>>(xg, Whh1, c0 + BB * HH, o1, state_out, 1);

    // ---- FC: logits = out1 @ Wfc^T + bfc (HMMA, Kexp=3072)
    split3<0><<<(M_ROWS * HH / 4 + 255) / 256, 256>>>(o1, nullptr, a2, M_ROWS * HH / 4, HH / 4);
    hmma_tn<false, false><<<dim3(M_ROWS / 128, VV / 128), 256, HM_SMEM>>>(
        a2, b2, bfc, nullptr, out, 3 * HH, VV);
}

// round 16
// speedup vs baseline: 2.3323x; 1.0477x over previous
#include <cuda_runtime.h>
#include <cuda_bf16.h>
#include <cstdint>

// ---------------- problem constants ----------------
#define T_SEQ 512
#define BB    16
#define HH    1024
#define EE    512
#define VV    32000
#define G4H   4096
#define M_ROWS (BB * T_SEQ)                     // 8192
#define LOGN  ((size_t)M_ROWS * (size_t)VV)     // 262,144,000

// ---------------- device scratch (static globals: allowed) ----------------
__device__ float g_xg[(size_t)T_SEQ * BB * G4H];      // 134 MB, reused per layer
__device__ float g_out0[(size_t)M_ROWS * HH];         // layer-0 h sequence
__device__ float g_out1[(size_t)M_ROWS * HH];         // layer-1 h sequence
__device__ __nv_bfloat16 g_hH[2 * BB * HH];           // h hi, [cur][b][j]
__device__ __nv_bfloat16 g_hL[2 * BB * HH];           // h lo, [cur][b][j]
__device__ unsigned g_bar;                            // zero-init
__device__ volatile unsigned g_epoch;                 // zero-init
__device__ __nv_bfloat16 g_A2[(size_t)M_ROWS * 3072]; // 50 MB  activations (hi|hi|lo)
__device__ __nv_bfloat16 g_B2[(size_t)VV * 3072];     // 197 MB Wfc (hi|lo|hi)
__device__ __nv_bfloat16 g_W2[(size_t)G4H * 3072];    // 25 MB  Wih (hi|lo|hi)

// ---------------- base-ISA async-copy / ldmatrix / mma helpers ----------------
__device__ __forceinline__ uint32_t smem_u32(const void* p) {
    uint32_t a;
    asm("{ .reg .u64 t; cvta.to.shared.u64 t, %1; cvt.u32.u64 %0, t; }" : "=r"(a) : "l"(p));
    return a;
}
__device__ __forceinline__ void cpa16(uint32_t dst, const void* src) {
    asm volatile("cp.async.cg.shared.global [%0], [%1], 16;" :: "r"(dst), "l"(src));
}
__device__ __forceinline__ void cpa_commit() { asm volatile("cp.async.commit_group;" ::: "memory"); }
template<int N> __device__ __forceinline__ void cpa_wait() {
    asm volatile("cp.async.wait_group %0;" :: "n"(N) : "memory");
}
__device__ __forceinline__ void ldsm4(uint32_t& r0, uint32_t& r1, uint32_t& r2, uint32_t& r3,
                                      uint32_t a) {
    asm volatile("ldmatrix.sync.aligned.m8n8.x4.shared.b16 {%0,%1,%2,%3}, [%4];"
                 : "=r"(r0), "=r"(r1), "=r"(r2), "=r"(r3) : "r"(a));
}
__device__ __forceinline__ void mma_bf16(float* c, const uint32_t* a, const uint32_t* b) {
    asm volatile(
        "mma.sync.aligned.m16n8k16.row.col.f32.bf16.bf16.f32 "
        "{%0,%1,%2,%3}, {%4,%5,%6,%7}, {%8,%9}, {%0,%1,%2,%3};"
        : "+f"(c[0]), "+f"(c[1]), "+f"(c[2]), "+f"(c[3])
        : "r"(a[0]), "r"(a[1]), "r"(a[2]), "r"(a[3]), "r"(b[0]), "r"(b[1]));
}

// ---------------- split-expand: fp32 [rows][K] -> bf16 [rows][3K] ---------------
// MODE 0 (activations): segs (hi, hi, lo).  MODE 1 (weights): segs (hi, lo, hi).
template<int MODE>
__global__ __launch_bounds__(256)
void split3(const float* __restrict__ src, const int* __restrict__ gidx,
            __nv_bfloat16* __restrict__ dst, int n4, int Kdiv4)
{
    int i = blockIdx.x * 256 + threadIdx.x;
    if (i >= n4) return;
    int row = i / Kdiv4;
    int c4  = i - row * Kdiv4;
    int K   = Kdiv4 * 4;
    const float* sp = gidx ? (src + (size_t)gidx[row] * K) : (src + (size_t)row * K);
    float4 v = *(const float4*)(sp + c4 * 4);
    __nv_bfloat16 h0 = __float2bfloat16(v.x), h1 = __float2bfloat16(v.y);
    __nv_bfloat16 h2 = __float2bfloat16(v.z), h3 = __float2bfloat16(v.w);
    __nv_bfloat16 l0 = __float2bfloat16(v.x - __bfloat162float(h0));
    __nv_bfloat16 l1 = __float2bfloat16(v.y - __bfloat162float(h1));
    __nv_bfloat16 l2 = __float2bfloat16(v.z - __bfloat162float(h2));
    __nv_bfloat16 l3 = __float2bfloat16(v.w - __bfloat162float(h3));
    __nv_bfloat162 hA(h0, h1), hB(h2, h3), lA(l0, l1), lB(l2, l3);
    size_t base = (size_t)row * (3 * K) + c4 * 4;
    __nv_bfloat162* d0 = (__nv_bfloat162*)(dst + base);
    __nv_bfloat162* d1 = (__nv_bfloat162*)(dst + base + K);
    __nv_bfloat162* d2 = (__nv_bfloat162*)(dst + base + 2 * K);
    d0[0] = hA; d0[1] = hB;
    if (MODE == 0) { d1[0] = hA; d1[1] = hB; d2[0] = lA; d2[1] = lB; }
    else           { d1[0] = lA; d1[1] = lB; d2[0] = hA; d2[1] = hB; }
}

// ---------------- generic HMMA GEMM (mma.sync bf16) ----------------------------
#define HM_BK      32
#define HM_STAGE_B 16384
#define HM_SMEM    (3 * HM_STAGE_B)     // 49152

__device__ __forceinline__ void hm_fill(uint32_t st, const __nv_bfloat16* a,
                                        const __nv_bfloat16* b, int tid, int Kexp)
{
#pragma unroll
    for (int i = tid; i < 512; i += 256) {
        int r = i >> 2, c = i & 3;
        uint32_t dst = st + r * 64 + ((c ^ ((r >> 1) & 3)) << 4);
        cpa16(dst, a + (size_t)r * Kexp + c * 8);
    }
#pragma unroll
    for (int i = tid; i < 512; i += 256) {
        int r = i >> 2, c = i & 3;
        uint32_t dst = st + 8192 + r * 64 + ((c ^ ((r >> 1) & 3)) << 4);
        cpa16(dst, b + (size_t)r * Kexp + c * 8);
    }
    cpa_commit();
}

template<bool REMAP, bool BIAS2>
__global__ __launch_bounds__(256, 2)
void hmma_tn(const __nv_bfloat16* __restrict__ A2, const __nv_bfloat16* __restrict__ B2,
             const float* __restrict__ bias1, const float* __restrict__ bias2,
             float* __restrict__ C, int Kexp, int N)
{
    extern __shared__ char smem[];
    const uint32_t sbase = smem_u32(smem);
    const int tid = threadIdx.x, wid = tid >> 5, lane = tid & 31;
    const int warp_m = wid & 1, warp_n = wid >> 1;
    const int m0 = blockIdx.x * 128;
    const int n0 = blockIdx.y * 128;

    const __nv_bfloat16* aG = A2 + (size_t)m0 * Kexp;
    const __nv_bfloat16* bG = B2 + (size_t)n0 * Kexp;

    uint32_t aoff[4][2], boff[2][2];
#pragma unroll
    for (int mi = 0; mi < 4; ++mi)
#pragma unroll
        for (int ks = 0; ks < 2; ++ks) {
            int row = warp_m * 64 + mi * 16 + (lane & 15);
            int ch  = ks * 2 + (lane >> 4);
            aoff[mi][ks] = row * 64 + ((ch ^ ((row >> 1) & 3)) << 4);
        }
#pragma unroll
    for (int bi = 0; bi < 2; ++bi)
#pragma unroll
        for (int ks = 0; ks < 2; ++ks) {
            int row = warp_n * 32 + bi * 16 + (lane & 7) + ((lane >> 4) << 3);
            int ch  = ks * 2 + ((lane >> 3) & 1);
            boff[bi][ks] = 8192 + row * 64 + ((ch ^ ((row >> 1) & 3)) << 4);
        }

    float acc[4][4][4];
#pragma unroll
    for (int i = 0; i < 4; i++)
#pragma unroll
        for (int j = 0; j < 4; j++)
#pragma unroll
            for (int e = 0; e < 4; e++) acc[i][j][e] = 0.f;

    const int NKB = Kexp / HM_BK;
    hm_fill(sbase,              aG,         bG,         tid, Kexp);
    hm_fill(sbase + HM_STAGE_B, aG + HM_BK, bG + HM_BK, tid, Kexp);

    for (int kb = 0; kb < NKB; ++kb) {
        const int s = kb % 3;
        cpa_wait<1>();
        __syncthreads();
        if (kb + 2 < NKB)
            hm_fill(sbase + ((kb + 2) % 3) * HM_STAGE_B,
                    aG + (size_t)(kb + 2) * HM_BK, bG + (size_t)(kb + 2) * HM_BK, tid, Kexp);

        const uint32_t sb = sbase + s * HM_STAGE_B;
#pragma unroll
        for (int ks = 0; ks < 2; ++ks) {
            uint32_t a[4][4], b[2][4];
#pragma unroll
            for (int mi = 0; mi < 4; ++mi)
                ldsm4(a[mi][0], a[mi][1], a[mi][2], a[mi][3], sb + aoff[mi][ks]);
#pragma unroll
            for (int bi = 0; bi < 2; ++bi)
                ldsm4(b[bi][0], b[bi][1], b[bi][2], b[bi][3], sb + boff[bi][ks]);
#pragma unroll
            for (int mi = 0; mi < 4; ++mi)
#pragma unroll
                for (int ni = 0; ni < 4; ++ni)
                    mma_bf16(acc[mi][ni], a[mi], &b[ni >> 1][(ni & 1) * 2]);
        }
        __syncthreads();
    }

#pragma unroll
    for (int mi = 0; mi < 4; ++mi) {
        int gm = m0 + warp_m * 64 + mi * 16 + (lane >> 2);
        size_t r0 = REMAP ? (size_t)((gm & (T_SEQ - 1)) * BB + (gm >> 9)) : (size_t)gm;
        int gm8 = gm + 8;
        size_t r1 = REMAP ? (size_t)((gm8 & (T_SEQ - 1)) * BB + (gm8 >> 9)) : (size_t)gm8;
#pragma unroll
        for (int ni = 0; ni < 4; ++ni) {
            int col = n0 + warp_n * 32 + ni * 8 + (lane & 3) * 2;
            float2 bv = *(const float2*)(bias1 + col);
            if (BIAS2) {
                float2 b2v = *(const float2*)(bias2 + col);
                bv.x += b2v.x; bv.y += b2v.y;
            }
            float2 v0; v0.x = acc[mi][ni][0] + bv.x; v0.y = acc[mi][ni][1] + bv.y;
            float2 v1; v1.x = acc[mi][ni][2] + bv.x; v1.y = acc[mi][ni][3] + bv.y;
            *(float2*)(C + r0 * (size_t)N + col) = v0;
            *(float2*)(C + r1 * (size_t)N + col) = v1;
        }
    }
}

// ---------------- h0 fill: bf16 hi/lo, [b][j], buffer 0 ------------------------
__global__ void fill_h0_kernel(const float* __restrict__ h0)
{
    int i = blockIdx.x * 256 + threadIdx.x;
    if (i < BB * HH) {
        float v = h0[i];
        __nv_bfloat16 hi = __float2bfloat16(v);
        __nv_bfloat16 lo = __float2bfloat16(v - __bfloat162float(hi));
        g_hH[i] = hi;
        g_hL[i] = lo;
    }
}

// ---------------- persistent LSTM scan (R15 + xg register prefetch) ------------
// smem: wsH [32r][1024k] bf16 swizzled 64KB @0 | wsL 64KB @65536
//       HsH per-warp [16n][136k] bf16 @131072 | HsL @165888 | red [8w][32r][16b] @200704
#define WS_BYTES  65536
#define HS_ROW    272
#define HS_WARP   (16 * HS_ROW)               // 4352
#define HSH_OFF   131072
#define HSL_OFF   (HSH_OFF + 8 * HS_WARP)     // 165888
#define RED_OFF   (HSL_OFF + 8 * HS_WARP)     // 200704
#define SCAN_SMEM (RED_OFF + 8 * 32 * 16 * 4) // 217088

__device__ __forceinline__ float sigm(float x) { return 1.f / (1.f + expf(-x)); }

__global__ __launch_bounds__(256)
void lstm_scan(const float* __restrict__ xg, const float* __restrict__ Whh,
               const float* __restrict__ c0, float* __restrict__ outSeq,
               float* __restrict__ state_out, int layer)
{
    extern __shared__ char smc[];
    const uint32_t sb = smem_u32(smc);
    float* red = (float*)(smc + RED_OFF);
    const int tid = threadIdx.x, cta = blockIdx.x;
    const int warp = tid >> 5, lane = tid & 31;

    // ---- init: convert Whh slice -> bf16 hi/lo, swizzled A layout (once) ----
    for (int idx = tid; idx < 32 * 128; idx += 256) {
        int r  = idx >> 7, ch = idx & 127;
        int grow = (r >> 3) * HH + cta * 8 + (r & 7);       // r = g*8 + jl
        const float* wp = Whh + (size_t)grow * HH + ch * 8;
        float4 f0 = *(const float4*)wp;
        float4 f1 = *(const float4*)(wp + 4);
        float v[8] = {f0.x, f0.y, f0.z, f0.w, f1.x, f1.y, f1.z, f1.w};
        uint32_t off = (uint32_t)(r * 2048 + ((ch ^ (r & 7)) << 4));
        __nv_bfloat162* dh = (__nv_bfloat162*)(smc + off);
        __nv_bfloat162* dl = (__nv_bfloat162*)(smc + WS_BYTES + off);
#pragma unroll
        for (int p = 0; p < 4; ++p) {
            __nv_bfloat16 h0b = __float2bfloat16(v[p * 2]);
            __nv_bfloat16 h1b = __float2bfloat16(v[p * 2 + 1]);
            __nv_bfloat16 l0b = __float2bfloat16(v[p * 2]     - __bfloat162float(h0b));
            __nv_bfloat16 l1b = __float2bfloat16(v[p * 2 + 1] - __bfloat162float(h1b));
            dh[p] = __nv_bfloat162(h0b, h1b);
            dl[p] = __nv_bfloat162(l0b, l1b);
        }
    }

    const int fb = tid >> 3, fj = tid & 7;
    float c_reg = 0.f;
    if (tid < 128) c_reg = c0[fb * HH + cta * 8 + fj];
    __syncthreads();                                   // ws ready

    // precomputed ldmatrix lane offsets (A chunks: this warp's k-slice)
    uint32_t aoff[2][8];
#pragma unroll
    for (int mi = 0; mi < 2; ++mi)
#pragma unroll
        for (int ks = 0; ks < 8; ++ks) {
            int row = mi * 16 + (lane & 15);
            int ch  = warp * 16 + ks * 2 + (lane >> 4);
            aoff[mi][ks] = (uint32_t)(row * 2048 + ((ch ^ (row & 7)) << 4));
        }
    uint32_t boff[8];
#pragma unroll
    for (int ks = 0; ks < 8; ++ks) {
        int nrow = (lane & 7) + ((lane >> 4) << 3);
        int ch   = ks * 2 + ((lane >> 3) & 1);
        boff[ks] = (uint32_t)(HSH_OFF + warp * HS_WARP + nrow * HS_ROW + ch * 16);
    }

    int cur = 0;
    const int k0 = warp * 128;
    for (int t = 0; t < T_SEQ; ++t) {
        // xg prefetch into registers (independent of h; hides under stage+mma)
        float xpre0 = 0.f, xpre1 = 0.f, xpre2 = 0.f, xpre3 = 0.f;
        if (tid < 128) {
            const float* xp = xg + (size_t)(t * BB + fb) * G4H + cta * 8 + fj;
            xpre0 = __ldcg(xp);
            xpre1 = __ldcg(xp + HH);
            xpre2 = __ldcg(xp + 2 * HH);
            xpre3 = __ldcg(xp + 3 * HH);
        }

        // stage own k-slice of h (bf16 hi/lo) into per-warp Hs
        {
            const __nv_bfloat16* hHsrc = g_hH + (size_t)cur * (BB * HH) + k0;
            const __nv_bfloat16* hLsrc = g_hL + (size_t)cur * (BB * HH) + k0;
            char* dH = smc + HSH_OFF + warp * HS_WARP + lane * 8;
            char* dL = smc + HSL_OFF + warp * HS_WARP + lane * 8;
#pragma unroll
            for (int b = 0; b < 16; ++b) {
                uint2 vh = __ldcg((const uint2*)(hHsrc + b * HH) + lane);
                uint2 vl = __ldcg((const uint2*)(hLsrc + b * HH) + lane);
                *(uint2*)(dH + b * HS_ROW) = vh;
                *(uint2*)(dL + b * HS_ROW) = vl;
            }
        }
        __syncwarp();

        float D[2][2][4];
#pragma unroll
        for (int mi = 0; mi < 2; ++mi)
#pragma unroll
            for (int ni = 0; ni < 2; ++ni)
#pragma unroll
                for (int e = 0; e < 4; ++e) D[mi][ni][e] = 0.f;

#pragma unroll
        for (int ks = 0; ks < 8; ++ks) {
            uint32_t ah[2][4], al[2][4], bh[4], bl[4];
#pragma unroll
            for (int mi = 0; mi < 2; ++mi) {
                ldsm4(ah[mi][0], ah[mi][1], ah[mi][2], ah[mi][3], sb + aoff[mi][ks]);
                ldsm4(al[mi][0], al[mi][1], al[mi][2], al[mi][3], sb + WS_BYTES + aoff[mi][ks]);
            }
            ldsm4(bh[0], bh[1], bh[2], bh[3], sb + boff[ks]);
            ldsm4(bl[0], bl[1], bl[2], bl[3], sb + boff[ks] + (HSL_OFF - HSH_OFF));
#pragma unroll
            for (int mi = 0; mi < 2; ++mi)
#pragma unroll
                for (int ni = 0; ni < 2; ++ni) {
                    mma_bf16(D[mi][ni], ah[mi], &bh[ni * 2]);
                    mma_bf16(D[mi][ni], al[mi], &bh[ni * 2]);
                    mma_bf16(D[mi][ni], ah[mi], &bl[ni * 2]);
                    mma_bf16(D[mi][ni], al[mi], &bl[ni * 2]);
                }
        }

        // write partials: red[warp][r][b]
        {
            float* rp = red + warp * 512;
#pragma unroll
            for (int mi = 0; mi < 2; ++mi)
#pragma unroll
                for (int ni = 0; ni < 2; ++ni) {
                    int r0 = mi * 16 + (lane >> 2);
                    int cb = ni * 8 + (lane & 3) * 2;
                    *(float2*)(rp + r0 * 16 + cb)       = make_float2(D[mi][ni][0], D[mi][ni][1]);
                    *(float2*)(rp + (r0 + 8) * 16 + cb) = make_float2(D[mi][ni][2], D[mi][ni][3]);
                }
        }
        __syncthreads();

        if (tid < 128) {
            int jg = cta * 8 + fj;
            float s[4];
#pragma unroll
            for (int g = 0; g < 4; ++g) {
                int base = (g * 8 + fj) * 16 + fb;
                float sum = 0.f;
#pragma unroll
                for (int w = 0; w < 8; ++w) sum += red[w * 512 + base];
                s[g] = sum;
            }
            s[0] += xpre0; s[1] += xpre1; s[2] += xpre2; s[3] += xpre3;
            float ci = sigm(s[0]), cf = sigm(s[1]);
            float cg = tanhf(s[2]), co = sigm(s[3]);
            c_reg = cf * c_reg + ci * cg;
            float hnew = co * tanhf(c_reg);
            outSeq[((size_t)fb * T_SEQ + t) * HH + jg] = hnew;
            __nv_bfloat16 hhi = __float2bfloat16(hnew);
            __nv_bfloat16 hlo = __float2bfloat16(hnew - __bfloat162float(hhi));
            size_t hoff = (size_t)(cur ^ 1) * (BB * HH) + fb * HH + jg;
            g_hH[hoff] = hhi;
            g_hL[hoff] = hlo;
            if (t == T_SEQ - 1 && state_out) {
                state_out[(size_t)layer * BB * HH + fb * HH + jg] = hnew;
                state_out[2 * (size_t)BB * HH + (size_t)layer * BB * HH + fb * HH + jg] = c_reg;
            }
        }

        // ---- R5 grid barrier (sense-reversal; validated) ----
        __syncthreads();
        if (tid == 0) {
            unsigned e = g_epoch;
            __threadfence();
            if (atomicAdd(&g_bar, 1u) == (unsigned)gridDim.x - 1u) {
                g_bar = 0;
                __threadfence();
                g_epoch = e + 1;
            } else {
                while (g_epoch == e) { }
            }
        }
        __syncthreads();
        cur ^= 1;
    }
}

// ---------------- launch -------------------------------------------------------
extern "C" void kernel_launch(void* const* d_in, const int* in_sizes, int n_in,
                              void* d_out, int out_size)
{
    const int*   x    = (const int*)  d_in[0];
    const float* h0   = (const float*)d_in[1];
    const float* c0   = (const float*)d_in[2];
    const float* emb  = (const float*)d_in[3];
    const float* Wih0 = (const float*)d_in[4];
    const float* Whh0 = (const float*)d_in[5];
    const float* bih0 = (const float*)d_in[6];
    const float* bhh0 = (const float*)d_in[7];
    const float* Wih1 = (const float*)d_in[8];
    const float* Whh1 = (const float*)d_in[9];
    const float* bih1 = (const float*)d_in[10];
    const float* bhh1 = (const float*)d_in[11];
    const float* Wfc  = (const float*)d_in[12];
    const float* bfc  = (const float*)d_in[13];
    float* out = (float*)d_out;

    float *xg, *o0, *o1;
    cudaGetSymbolAddress((void**)&xg, g_xg);
    cudaGetSymbolAddress((void**)&o0, g_out0);
    cudaGetSymbolAddress((void**)&o1, g_out1);
    __nv_bfloat16 *a2, *b2, *w2;
    cudaGetSymbolAddress((void**)&a2, g_A2);
    cudaGetSymbolAddress((void**)&b2, g_B2);
    cudaGetSymbolAddress((void**)&w2, g_W2);

    float* state_out = ((size_t)out_size >= LOGN + 4 * BB * HH) ? (out + LOGN) : nullptr;

    cudaFuncSetAttribute(lstm_scan, cudaFuncAttributeMaxDynamicSharedMemorySize, SCAN_SMEM);
    cudaFuncSetAttribute(hmma_tn<true, true>,   cudaFuncAttributeMaxDynamicSharedMemorySize, HM_SMEM);
    cudaFuncSetAttribute(hmma_tn<false, false>, cudaFuncAttributeMaxDynamicSharedMemorySize, HM_SMEM);

    // Wfc split (hi|lo|hi) — biggest split, up front
    split3<1><<<(VV * HH / 4 + 255) / 256, 256>>>(Wfc, nullptr, b2, VV * HH / 4, HH / 4);

    // ---- layer 0: xg0 = gather(emb,x) @ Wih0^T + bih0 + bhh0 (HMMA, Kexp=1536)
    split3<0><<<(M_ROWS * EE / 4 + 255) / 256, 256>>>(emb, x, a2, M_ROWS * EE / 4, EE / 4);
    split3<1><<<(G4H * EE / 4 + 255) / 256, 256>>>(Wih0, nullptr, w2, G4H * EE / 4, EE / 4);
    hmma_tn<true, true><<<dim3(M_ROWS / 128, G4H / 128), 256, HM_SMEM>>>(
        a2, w2, bih0, bhh0, xg, 3 * EE, G4H);
    fill_h0_kernel<<<(BB * HH + 255) / 256, 256>>>(h0);
    lstm_scan<<<128, 256, SCAN_SMEM>>>(xg, Whh0, c0, o0, state_out, 0);

    // ---- layer 1: xg1 = out0 @ Wih1^T + bih1 + bhh1 (HMMA, Kexp=3072)
    split3<0><<<(M_ROWS * HH / 4 + 255) / 256, 256>>>(o0, nullptr, a2, M_ROWS * HH / 4, HH / 4);
    split3<1><<<(G4H * HH / 4 + 255) / 256, 256>>>(Wih1, nullptr, w2, G4H * HH / 4, HH / 4);
    hmma_tn<true, true><<<dim3(M_ROWS / 128, G4H / 128), 256, HM_SMEM>>>(
        a2, w2, bih1, bhh1, xg, 3 * HH, G4H);
    fill_h0_kernel<<<(BB * HH + 255) / 256, 256>>>(h0 + BB * HH);
    lstm_scan<<<128, 256, SCAN_SMEM>>>(xg, Whh1, c0 + BB * HH, o1, state_out, 1);

    // ---- FC: logits = out1 @ Wfc^T + bfc (HMMA, Kexp=3072)
    split3<0><<<(M_ROWS * HH / 4 + 255) / 256, 256>>>(o1, nullptr, a2, M_ROWS * HH / 4, HH / 4);
    hmma_tn<false, false><<<dim3(M_ROWS / 128, VV / 128), 256, HM_SMEM>>>(
        a2, b2, bfc, nullptr, out, 3 * HH, VV);
}